// round 5
// baseline (speedup 1.0000x reference)
#include <cuda_runtime.h>
#include <cstdint>
#include <math.h>

#define BATCH 2
#define SEQ   2048
#define NH    16
#define DK    64
#define DM    1024
#define MTOT  4096
#define KT    64
#define NT    32

#define STD_OFF  4194304ull
#define SPEC_OFF 104857600ull

// ------------- scratch (no allocations allowed) -------------
__device__ float g_xr[(size_t)MTOT*DM];             // tf32(x)
__device__ float g_wt[(size_t)4*DM*DM];             // W^T tf32 (q,k,v,o)
__device__ float g_q [(size_t)BATCH*NH*SEQ*DK];     // [B,H,S,Dk] tf32
__device__ float g_k [(size_t)BATCH*NH*SEQ*DK];
__device__ float g_vt[(size_t)BATCH*NH*DK*SEQ];     // [B,H,Dk,S] tf32
__device__ float g_attn[(size_t)MTOT*DM];           // fp32

// ------------- helpers -------------
__device__ __forceinline__ float to_tf32(float x) {
    float r; asm("cvt.rna.tf32.f32 %0, %1;" : "=f"(r) : "f"(x)); return r;
}
__device__ __forceinline__ uint32_t smem_u32(const void* p) {
    uint32_t a;
    asm("{ .reg .u64 t; cvta.to.shared.u64 t, %1; cvt.u32.u64 %0, t; }" : "=r"(a) : "l"(p));
    return a;
}
#define CPA(d, s) asm volatile("cp.async.cg.shared.global [%0], [%1], 16;" :: "r"(d), "l"(s))
#define CPC()  asm volatile("cp.async.commit_group;")
#define CPW0() asm volatile("cp.async.wait_group 0;" ::: "memory")
#define CPW1() asm volatile("cp.async.wait_group 1;" ::: "memory")

#define MMA8(d, a, b) \
    asm volatile("mma.sync.aligned.m16n8k8.row.col.f32.tf32.tf32.f32 " \
        "{%0,%1,%2,%3}, {%4,%5,%6,%7}, {%8,%9}, {%0,%1,%2,%3};" \
        : "+f"((d)[0]), "+f"((d)[1]), "+f"((d)[2]), "+f"((d)[3]) \
        : "r"((a)[0]), "r"((a)[1]), "r"((a)[2]), "r"((a)[3]), "r"((b)[0]), "r"((b)[1]))

// swizzled float index within a panel of 32-float rows
__device__ __forceinline__ int swi(int row, int kk) {
    return row * 32 + (((kk >> 2) ^ (row & 7)) << 2) + (kk & 3);
}
// byte addr for cp.async dst, panel of 32-float rows
__device__ __forceinline__ uint32_t swc(uint32_t base, int row, int c) {
    return base + row * 128 + ((c ^ (row & 7)) << 4);
}

__device__ __forceinline__ float* head_w_ptr(float* dout, int bh) {
    int b = bh >> 4, h = bh & 15;
    size_t off;
    if (h < 12) off = STD_OFF  + ((size_t)(b * 12 + h)) * SEQ * SEQ;
    else        off = SPEC_OFF + ((size_t)(b * 4 + (h - 12))) * SEQ * SEQ;
    return dout + off;
}

// ---------------------------------------------------------------------------
__global__ __launch_bounds__(256) void round_x(const float4* __restrict__ x)
{
    int i = blockIdx.x * 256 + threadIdx.x;
    float4 v = x[i];
    v.x = to_tf32(v.x); v.y = to_tf32(v.y); v.z = to_tf32(v.z); v.w = to_tf32(v.w);
    ((float4*)g_xr)[i] = v;
}

__global__ __launch_bounds__(256) void transpose_w(
    const float* __restrict__ w0, const float* __restrict__ w1,
    const float* __restrict__ w2, const float* __restrict__ w3)
{
    __shared__ float t[32][33];
    int z = blockIdx.z;
    const float* src = (z == 0) ? w0 : (z == 1) ? w1 : (z == 2) ? w2 : w3;
    float* dst = g_wt + (size_t)z * DM * DM;
    int x = blockIdx.x * 32 + threadIdx.x;
    int y0 = blockIdx.y * 32;
    for (int i = threadIdx.y; i < 32; i += 8)
        t[i][threadIdx.x] = src[(size_t)(y0 + i) * DM + x];
    __syncthreads();
    int kx = y0 + threadIdx.x;
    int n0 = blockIdx.x * 32;
    for (int i = threadIdx.y; i < 32; i += 8)
        dst[(size_t)(n0 + i) * DM + kx] = to_tf32(t[threadIdx.x][i]);
}

// ---------------------------------------------------------------------------
// Projection GEMM: C[4096,1024] = A @ W^T + bias. Block 128x128, K=1024.
// mode 0: QKV fused (which = blockIdx.z in {0,1,2}); mode 3: out-proj.
// ---------------------------------------------------------------------------
__global__ __launch_bounds__(256, 2) void proj_mm(
    const float* __restrict__ b0, const float* __restrict__ b1,
    const float* __restrict__ b2, float* __restrict__ Cout, int mode)
{
    extern __shared__ float sm[];
    uint32_t smb = smem_u32(sm);
    const int tid = threadIdx.x;
    const int w = tid >> 5, lane = tid & 31, g = lane >> 2, tg = lane & 3;
    const int wm = w >> 2, wn = w & 3;
    const int bn = blockIdx.x * 128, bm = blockIdx.y * 128;
    const int which = (mode == 3) ? 3 : (int)blockIdx.z;
    const float* bias = (which == 0) ? b0 : (which == 1) ? b1 : (which == 2) ? b2 : b0;
    const float* Ap = (which == 3) ? (const float*)g_attn : (const float*)g_xr;
    const float* Wt = g_wt + (size_t)which * DM * DM;

    float acc[4][4][4];
#pragma unroll
    for (int i = 0; i < 4; i++)
#pragma unroll
        for (int j = 0; j < 4; j++)
#pragma unroll
            for (int e = 0; e < 4; e++) acc[i][j][e] = 0.f;

    const int r8 = tid >> 3, c8 = tid & 7;
    auto load = [&](int c, int buf) {
        const float* as = Ap + (size_t)bm * DM + c * 32;
        const float* bs = Wt + (size_t)bn * DM + c * 32;
        uint32_t ab = smb + buf * 16384, bb = smb + 32768 + buf * 16384;
#pragma unroll
        for (int j = 0; j < 4; j++) {
            int r = r8 + 32 * j;
            CPA(swc(ab, r, c8), as + (size_t)r * DM + c8 * 4);
            CPA(swc(bb, r, c8), bs + (size_t)r * DM + c8 * 4);
        }
        CPC();
    };
    auto compute = [&](int buf) {
        const float* A = sm + buf * 4096;
        const float* B = sm + 8192 + buf * 4096;
#pragma unroll
        for (int ks = 0; ks < 4; ks++) {
            int k0 = ks * 8;
            uint32_t a[4][4], b[4][2];
#pragma unroll
            for (int mf = 0; mf < 4; mf++) {
                int row = wm * 64 + mf * 16 + g;
                a[mf][0] = __float_as_uint(A[swi(row,     k0 + tg)]);
                a[mf][1] = __float_as_uint(A[swi(row + 8, k0 + tg)]);
                a[mf][2] = __float_as_uint(A[swi(row,     k0 + 4 + tg)]);
                a[mf][3] = __float_as_uint(A[swi(row + 8, k0 + 4 + tg)]);
            }
#pragma unroll
            for (int nf = 0; nf < 4; nf++) {
                int rn = wn * 32 + nf * 8 + g;
                b[nf][0] = __float_as_uint(B[swi(rn, k0 + tg)]);
                b[nf][1] = __float_as_uint(B[swi(rn, k0 + 4 + tg)]);
            }
#pragma unroll
            for (int mf = 0; mf < 4; mf++)
#pragma unroll
                for (int nf = 0; nf < 4; nf++)
                    MMA8(acc[mf][nf], a[mf], b[nf]);
        }
    };

    load(0, 0); load(1, 1);
    const int NC = DM / 32;
    for (int c = 0; c < NC; c++) {
        if (c < NC - 1) { CPW1(); } else { CPW0(); }
        __syncthreads();
        compute(c & 1);
        __syncthreads();
        if (c + 2 < NC) load(c + 2, c & 1);
    }

#pragma unroll
    for (int mf = 0; mf < 4; mf++)
#pragma unroll
    for (int half = 0; half < 2; half++) {
        int m = bm + wm * 64 + mf * 16 + g + half * 8;
#pragma unroll
        for (int nf = 0; nf < 4; nf++) {
            int n = bn + wn * 32 + nf * 8 + 2 * tg;
            float v0 = acc[mf][nf][2 * half]     + bias[n];
            float v1 = acc[mf][nf][2 * half + 1] + bias[n + 1];
            if (which == 3) {
                *(float2*)(Cout + (size_t)m * DM + n) = make_float2(v0, v1);
            } else {
                int b_ = m >> 11, s = m & 2047, h = n >> 6, d = n & 63;
                if (which == 2) {
                    g_vt[(((size_t)(b_ * NH + h)) * DK + d)     * SEQ + s] = to_tf32(v0);
                    g_vt[(((size_t)(b_ * NH + h)) * DK + d + 1) * SEQ + s] = to_tf32(v1);
                } else {
                    float* qk = which ? g_k : g_q;
                    *(float2*)(qk + (((size_t)(b_ * NH + h)) * SEQ + s) * DK + d) =
                        make_float2(to_tf32(v0), to_tf32(v1));
                }
            }
        }
    }
}

// ---------------------------------------------------------------------------
// Fused attention: CTA = (mtile of 128 q-rows, head). Warp = 16 rows.
// Sweep1: scores+exp -> rowsums. Sweep2: recompute, normalize, coalesced
// weight write, AV MMA (O^T = V^T @ E^T) from staged E, epilogue -> g_attn.
// dyn smem floats: Q[0,8192) K[8192,12288) V[12288,16384) stage[16384,+8*1088)
// ---------------------------------------------------------------------------
__global__ __launch_bounds__(256, 2) void attn_fused(float* __restrict__ dout)
{
    extern __shared__ float sm[];
    __shared__ float s_inv[128];
    uint32_t smb = smem_u32(sm);
    const int tid = threadIdx.x;
    const int w = tid >> 5, lane = tid & 31, g = lane >> 2, tg = lane & 3;
    const int mt = blockIdx.x, bh = blockIdx.y;
    const int m0 = mt * 128;
    const int b_ = bh >> 4, h = bh & 15;
    float* wp = head_w_ptr(dout, bh);
    const float* qsrc = g_q  + (size_t)bh * SEQ * DK;
    const float* ksrc = g_k  + (size_t)bh * SEQ * DK;
    const float* vsrc = g_vt + (size_t)bh * DK * SEQ;

    const int SQ = 0, SK = 8192, SV = 12288, ST = 16384;
    float* stg = sm + ST + w * 1088;   // per-warp [16][68]

    // ---- Q load: [128][64] as 2 panels of 128 rows ----
#pragma unroll
    for (int i = 0; i < 8; i++) {
        int idx = tid + i * 256;
        int r = idx >> 4, ch = idx & 15;
        CPA(swc(smb + SQ * 4 + (ch >> 3) * 16384, r, ch & 7),
            qsrc + (size_t)(m0 + r) * DK + ch * 4);
    }
    CPC();

    auto loadK = [&](int t, int base_f) {
#pragma unroll
        for (int i = 0; i < 4; i++) {
            int idx = tid + i * 256;
            int r = idx >> 4, ch = idx & 15;
            CPA(swc(smb + base_f * 4 + (ch >> 3) * 8192, r, ch & 7),
                ksrc + (size_t)(t * KT + r) * DK + ch * 4);
        }
        CPC();
    };
    auto loadV = [&](int t) {
#pragma unroll
        for (int i = 0; i < 4; i++) {
            int idx = tid + i * 256;
            int d = idx >> 4, ch = idx & 15;
            CPA(swc(smb + SV * 4 + (ch >> 3) * 8192, d, ch & 7),
                vsrc + (size_t)d * SEQ + t * KT + ch * 4);
        }
        CPC();
    };
    // frag index: panel fold keeps row&7 intact for conflict-free LDS
    auto fq = [&](int r, int k) { return SQ + (k >> 5) * 4096 + swi(r, k & 31); };
    auto f64 = [&](int base_f, int r, int k) { return base_f + (k >> 5) * 2048 + swi(r, k & 31); };

    auto scores = [&](int kbase, float (&acc)[8][4]) {
#pragma unroll
        for (int nf = 0; nf < 8; nf++)
#pragma unroll
            for (int e = 0; e < 4; e++) acc[nf][e] = 0.f;
#pragma unroll
        for (int kc = 0; kc < 8; kc++) {
            int k0 = kc * 8 + tg;
            uint32_t a[4];
            a[0] = __float_as_uint(sm[fq(w * 16 + g,     k0)]);
            a[1] = __float_as_uint(sm[fq(w * 16 + g + 8, k0)]);
            a[2] = __float_as_uint(sm[fq(w * 16 + g,     k0 + 4)]);
            a[3] = __float_as_uint(sm[fq(w * 16 + g + 8, k0 + 4)]);
#pragma unroll
            for (int nf = 0; nf < 8; nf++) {
                uint32_t b[2];
                b[0] = __float_as_uint(sm[f64(kbase, nf * 8 + g, k0)]);
                b[1] = __float_as_uint(sm[f64(kbase, nf * 8 + g, k0 + 4)]);
                MMA8(acc[nf], a, b);
            }
        }
    };

    // ================= sweep 1: rowsums =================
    loadK(0, SK);
    float rs0 = 0.f, rs1 = 0.f;
    for (int t = 0; t < NT; t++) {
        CPW0(); __syncthreads();
        if (t + 1 < NT) loadK(t + 1, (t & 1) ? SK : SV);
        float acc[8][4];
        scores((t & 1) ? SV : SK, acc);
#pragma unroll
        for (int nf = 0; nf < 8; nf++) {
            rs0 += __expf(acc[nf][0] * 0.125f) + __expf(acc[nf][1] * 0.125f);
            rs1 += __expf(acc[nf][2] * 0.125f) + __expf(acc[nf][3] * 0.125f);
        }
        __syncthreads();
    }
    rs0 += __shfl_xor_sync(0xffffffffu, rs0, 1);
    rs0 += __shfl_xor_sync(0xffffffffu, rs0, 2);
    rs1 += __shfl_xor_sync(0xffffffffu, rs1, 1);
    rs1 += __shfl_xor_sync(0xffffffffu, rs1, 2);
    if (tg == 0) {
        s_inv[w * 16 + g]     = 1.0f / rs0;
        s_inv[w * 16 + g + 8] = 1.0f / rs1;
    }
    __syncthreads();
    const float inv0 = s_inv[w * 16 + g];
    const float inv1 = s_inv[w * 16 + g + 8];

    // ================= sweep 2: normalize+write+AV =================
    float oacc[4][2][4];
#pragma unroll
    for (int i = 0; i < 4; i++)
#pragma unroll
        for (int j = 0; j < 2; j++)
#pragma unroll
            for (int e = 0; e < 4; e++) oacc[i][j][e] = 0.f;

    loadK(0, SK);
    for (int t = 0; t < NT; t++) {
        CPW0(); __syncthreads();       // K_t ready
        loadV(t);
        float acc[8][4];
        scores(SK, acc);
        // normalized E -> warp-private stage
#pragma unroll
        for (int nf = 0; nf < 8; nf++) {
            float e0 = __expf(acc[nf][0] * 0.125f) * inv0;
            float e1 = __expf(acc[nf][1] * 0.125f) * inv0;
            float e2 = __expf(acc[nf][2] * 0.125f) * inv1;
            float e3 = __expf(acc[nf][3] * 0.125f) * inv1;
            *(float2*)&stg[g * 68 + nf * 8 + 2 * tg]       = make_float2(e0, e1);
            *(float2*)&stg[(g + 8) * 68 + nf * 8 + 2 * tg] = make_float2(e2, e3);
        }
        __syncwarp();
        // coalesced weight write (full fp32)
#pragma unroll
        for (int i = 0; i < 8; i++) {
            int idx = lane + i * 32;
            int q = idx >> 4, c = (idx & 15) * 4;
            float4 v = *(float4*)&stg[q * 68 + c];
            *(float4*)&wp[(size_t)(m0 + w * 16 + q) * SEQ + t * KT + c] = v;
        }
        CPW0(); __syncthreads();       // V_t ready, all warps done with sK
        if (t + 1 < NT) loadK(t + 1, SK);
        // AV: O^T += V^T(tile) @ E^T
#pragma unroll
        for (int kc = 0; kc < 8; kc++) {
            int k0 = kc * 8 + tg;
            uint32_t bf[2][2];
#pragma unroll
            for (int qc = 0; qc < 2; qc++) {
                bf[qc][0] = __float_as_uint(to_tf32(stg[(qc * 8 + g) * 68 + k0]));
                bf[qc][1] = __float_as_uint(to_tf32(stg[(qc * 8 + g) * 68 + k0 + 4]));
            }
#pragma unroll
            for (int mf = 0; mf < 4; mf++) {
                uint32_t a[4];
                a[0] = __float_as_uint(sm[f64(SV, mf * 16 + g,     k0)]);
                a[1] = __float_as_uint(sm[f64(SV, mf * 16 + g + 8, k0)]);
                a[2] = __float_as_uint(sm[f64(SV, mf * 16 + g,     k0 + 4)]);
                a[3] = __float_as_uint(sm[f64(SV, mf * 16 + g + 8, k0 + 4)]);
#pragma unroll
                for (int qc = 0; qc < 2; qc++) MMA8(oacc[mf][qc], a, bf[qc]);
            }
        }
    }

    // ---- epilogue: O^T -> stage transpose -> g_attn ----
    __syncwarp();
#pragma unroll
    for (int mf = 0; mf < 4; mf++)
#pragma unroll
        for (int qc = 0; qc < 2; qc++) {
            stg[(qc * 8 + 2 * tg) * 68     + mf * 16 + g]     = oacc[mf][qc][0];
            stg[(qc * 8 + 2 * tg + 1) * 68 + mf * 16 + g]     = oacc[mf][qc][1];
            stg[(qc * 8 + 2 * tg) * 68     + mf * 16 + g + 8] = oacc[mf][qc][2];
            stg[(qc * 8 + 2 * tg + 1) * 68 + mf * 16 + g + 8] = oacc[mf][qc][3];
        }
    __syncwarp();
#pragma unroll
    for (int i = 0; i < 8; i++) {
        int idx = lane + i * 32;
        int q = idx >> 4, c = (idx & 15) * 4;
        float4 v = *(float4*)&stg[q * 68 + c];
        *(float4*)&g_attn[((size_t)b_ * SEQ + m0 + w * 16 + q) * DM + h * DK + c] = v;
    }
}

// ---------------------------------------------------------------------------
extern "C" void kernel_launch(void* const* d_in, const int* in_sizes, int n_in,
                              void* d_out, int out_size)
{
    const float* x  = (const float*)d_in[0];
    const float* Wq = (const float*)d_in[2];
    const float* bq = (const float*)d_in[3];
    const float* Wk = (const float*)d_in[4];
    const float* bk = (const float*)d_in[5];
    const float* Wv = (const float*)d_in[6];
    const float* bv = (const float*)d_in[7];
    const float* Wo = (const float*)d_in[8];
    const float* bo = (const float*)d_in[9];
    float* out = (float*)d_out;

    cudaFuncSetAttribute(proj_mm,    cudaFuncAttributeMaxDynamicSharedMemorySize, 65536);
    cudaFuncSetAttribute(attn_fused, cudaFuncAttributeMaxDynamicSharedMemorySize, 100352);

    round_x<<<4096, 256>>>((const float4*)x);
    transpose_w<<<dim3(32, 32, 4), dim3(32, 8)>>>(Wq, Wk, Wv, Wo);

    proj_mm<<<dim3(8, 32, 3), 256, 65536>>>(bq, bk, bv, nullptr, 0);   // QKV fused
    attn_fused<<<dim3(16, 32), 256, 100352>>>(out);
    proj_mm<<<dim3(8, 32, 1), 256, 65536>>>(bo, bo, bo, out, 3);       // out-proj
}

// round 7
// speedup vs baseline: 1.2392x; 1.2392x over previous
#include <cuda_runtime.h>
#include <cstdint>
#include <math.h>

#define BATCH 2
#define SEQ   2048
#define NH    16
#define DK    64
#define DM    1024
#define MTOT  4096
#define KT    64
#define NT    32

#define STD_OFF  4194304ull
#define SPEC_OFF 104857600ull

// ------------- scratch (no allocations allowed) -------------
__device__ float g_xr[(size_t)MTOT*DM];             // tf32(x)
__device__ float g_wt[(size_t)4*DM*DM];             // W^T tf32 (q,k,v,o)
__device__ float g_q [(size_t)BATCH*NH*SEQ*DK];     // [B,H,S,Dk] tf32
__device__ float g_k [(size_t)BATCH*NH*SEQ*DK];
__device__ float g_vt[(size_t)BATCH*NH*DK*SEQ];     // [B,H,Dk,S] tf32
__device__ float g_attn[(size_t)MTOT*DM];           // fp32
__device__ float g_psum[(size_t)16*BATCH*NH*SEQ];   // partial row sums per n-tile

// ------------- helpers -------------
__device__ __forceinline__ float to_tf32(float x) {
    float r; asm("cvt.rna.tf32.f32 %0, %1;" : "=f"(r) : "f"(x)); return r;
}
__device__ __forceinline__ uint32_t smem_u32(const void* p) {
    uint32_t a;
    asm("{ .reg .u64 t; cvta.to.shared.u64 t, %1; cvt.u32.u64 %0, t; }" : "=r"(a) : "l"(p));
    return a;
}
#define CPA(d, s) asm volatile("cp.async.cg.shared.global [%0], [%1], 16;" :: "r"(d), "l"(s))
#define CPC()  asm volatile("cp.async.commit_group;")
#define CPW0() asm volatile("cp.async.wait_group 0;" ::: "memory")
#define CPW1() asm volatile("cp.async.wait_group 1;" ::: "memory")

#define MMA8(d, a, b) \
    asm volatile("mma.sync.aligned.m16n8k8.row.col.f32.tf32.tf32.f32 " \
        "{%0,%1,%2,%3}, {%4,%5,%6,%7}, {%8,%9}, {%0,%1,%2,%3};" \
        : "+f"((d)[0]), "+f"((d)[1]), "+f"((d)[2]), "+f"((d)[3]) \
        : "r"((a)[0]), "r"((a)[1]), "r"((a)[2]), "r"((a)[3]), "r"((b)[0]), "r"((b)[1]))

__device__ __forceinline__ int swi(int row, int kk) {
    return row * 32 + (((kk >> 2) ^ (row & 7)) << 2) + (kk & 3);
}
__device__ __forceinline__ uint32_t swc(uint32_t base, int row, int c) {
    return base + row * 128 + ((c ^ (row & 7)) << 4);
}

__device__ __forceinline__ float* head_w_ptr(float* dout, int bh) {
    int b = bh >> 4, h = bh & 15;
    size_t off;
    if (h < 12) off = STD_OFF  + ((size_t)(b * 12 + h)) * SEQ * SEQ;
    else        off = SPEC_OFF + ((size_t)(b * 4 + (h - 12))) * SEQ * SEQ;
    return dout + off;
}

// ---------------------------------------------------------------------------
__global__ __launch_bounds__(256) void round_x(const float4* __restrict__ x)
{
    int i = blockIdx.x * 256 + threadIdx.x;
    float4 v = x[i];
    v.x = to_tf32(v.x); v.y = to_tf32(v.y); v.z = to_tf32(v.z); v.w = to_tf32(v.w);
    ((float4*)g_xr)[i] = v;
}

__global__ __launch_bounds__(256) void transpose_w(
    const float* __restrict__ w0, const float* __restrict__ w1,
    const float* __restrict__ w2, const float* __restrict__ w3)
{
    __shared__ float t[32][33];
    int z = blockIdx.z;
    const float* src = (z == 0) ? w0 : (z == 1) ? w1 : (z == 2) ? w2 : w3;
    float* dst = g_wt + (size_t)z * DM * DM;
    int x = blockIdx.x * 32 + threadIdx.x;
    int y0 = blockIdx.y * 32;
    for (int i = threadIdx.y; i < 32; i += 8)
        t[i][threadIdx.x] = src[(size_t)(y0 + i) * DM + x];
    __syncthreads();
    int kx = y0 + threadIdx.x;
    int n0 = blockIdx.x * 32;
    for (int i = threadIdx.y; i < 32; i += 8)
        dst[(size_t)(n0 + i) * DM + kx] = to_tf32(t[threadIdx.x][i]);
}

// ---------------------------------------------------------------------------
// Projection GEMM: C[4096,1024] = A @ W^T + bias. Block 128x128, K=1024.
// mode 0: QKV fused (which = blockIdx.z); mode 3: out-proj.
// ---------------------------------------------------------------------------
__global__ __launch_bounds__(256, 2) void proj_mm(
    const float* __restrict__ b0, const float* __restrict__ b1,
    const float* __restrict__ b2, float* __restrict__ Cout, int mode)
{
    extern __shared__ float sm[];
    uint32_t smb = smem_u32(sm);
    const int tid = threadIdx.x;
    const int w = tid >> 5, lane = tid & 31, g = lane >> 2, tg = lane & 3;
    const int wm = w >> 2, wn = w & 3;
    const int bn = blockIdx.x * 128, bm = blockIdx.y * 128;
    const int which = (mode == 3) ? 3 : (int)blockIdx.z;
    const float* bias = (which == 0) ? b0 : (which == 1) ? b1 : (which == 2) ? b2 : b0;
    const float* Ap = (which == 3) ? (const float*)g_attn : (const float*)g_xr;
    const float* Wt = g_wt + (size_t)which * DM * DM;

    float acc[4][4][4];
#pragma unroll
    for (int i = 0; i < 4; i++)
#pragma unroll
        for (int j = 0; j < 4; j++)
#pragma unroll
            for (int e = 0; e < 4; e++) acc[i][j][e] = 0.f;

    const int r8 = tid >> 3, c8 = tid & 7;
    auto load = [&](int c, int buf) {
        const float* as = Ap + (size_t)bm * DM + c * 32;
        const float* bs = Wt + (size_t)bn * DM + c * 32;
        uint32_t ab = smb + buf * 16384, bb = smb + 32768 + buf * 16384;
#pragma unroll
        for (int j = 0; j < 4; j++) {
            int r = r8 + 32 * j;
            CPA(swc(ab, r, c8), as + (size_t)r * DM + c8 * 4);
            CPA(swc(bb, r, c8), bs + (size_t)r * DM + c8 * 4);
        }
        CPC();
    };
    auto compute = [&](int buf) {
        const float* A = sm + buf * 4096;
        const float* B = sm + 8192 + buf * 4096;
#pragma unroll
        for (int ks = 0; ks < 4; ks++) {
            int k0 = ks * 8;
            uint32_t a[4][4], b[4][2];
#pragma unroll
            for (int mf = 0; mf < 4; mf++) {
                int row = wm * 64 + mf * 16 + g;
                a[mf][0] = __float_as_uint(A[swi(row,     k0 + tg)]);
                a[mf][1] = __float_as_uint(A[swi(row + 8, k0 + tg)]);
                a[mf][2] = __float_as_uint(A[swi(row,     k0 + 4 + tg)]);
                a[mf][3] = __float_as_uint(A[swi(row + 8, k0 + 4 + tg)]);
            }
#pragma unroll
            for (int nf = 0; nf < 4; nf++) {
                int rn = wn * 32 + nf * 8 + g;
                b[nf][0] = __float_as_uint(B[swi(rn, k0 + tg)]);
                b[nf][1] = __float_as_uint(B[swi(rn, k0 + 4 + tg)]);
            }
#pragma unroll
            for (int mf = 0; mf < 4; mf++)
#pragma unroll
                for (int nf = 0; nf < 4; nf++)
                    MMA8(acc[mf][nf], a[mf], b[nf]);
        }
    };

    load(0, 0); load(1, 1);
    const int NC = DM / 32;
    for (int c = 0; c < NC; c++) {
        if (c < NC - 1) { CPW1(); } else { CPW0(); }
        __syncthreads();
        compute(c & 1);
        __syncthreads();
        if (c + 2 < NC) load(c + 2, c & 1);
    }

#pragma unroll
    for (int mf = 0; mf < 4; mf++)
#pragma unroll
    for (int half = 0; half < 2; half++) {
        int m = bm + wm * 64 + mf * 16 + g + half * 8;
#pragma unroll
        for (int nf = 0; nf < 4; nf++) {
            int n = bn + wn * 32 + nf * 8 + 2 * tg;
            float v0 = acc[mf][nf][2 * half]     + bias[n];
            float v1 = acc[mf][nf][2 * half + 1] + bias[n + 1];
            if (which == 3) {
                *(float2*)(Cout + (size_t)m * DM + n) = make_float2(v0, v1);
            } else {
                int b_ = m >> 11, s = m & 2047, h = n >> 6, d = n & 63;
                if (which == 2) {
                    g_vt[(((size_t)(b_ * NH + h)) * DK + d)     * SEQ + s] = to_tf32(v0);
                    g_vt[(((size_t)(b_ * NH + h)) * DK + d + 1) * SEQ + s] = to_tf32(v1);
                } else {
                    float* qk = which ? g_k : g_q;
                    *(float2*)(qk + (((size_t)(b_ * NH + h)) * SEQ + s) * DK + d) =
                        make_float2(to_tf32(v0), to_tf32(v1));
                }
            }
        }
    }
}

// ---------------------------------------------------------------------------
// Kernel A: rowsum. Block = (ntile 128 keys, mtile 128 rows, head).
// Scores MMA + exp -> partial row sums only (no weight writes).
// smem floats: Q panels [0,8192), K panels [8192,16384)  (64KB)
// ---------------------------------------------------------------------------
__global__ __launch_bounds__(256, 2) void rowsum_k()
{
    extern __shared__ float sm[];
    uint32_t smb = smem_u32(sm);
    const int tid = threadIdx.x;
    const int w = tid >> 5, lane = tid & 31, g = lane >> 2, tg = lane & 3;
    const int nt = blockIdx.x, mt = blockIdx.y, bh = blockIdx.z;
    const int n0 = nt * 128, m0 = mt * 128;
    const float* qsrc = g_q + (size_t)bh * SEQ * DK;
    const float* ksrc = g_k + (size_t)bh * SEQ * DK;

#pragma unroll
    for (int j = 0; j < 8; j++) {
        int idx = tid + 256 * j;
        int r = idx >> 4, ch = idx & 15;
        CPA(swc(smb + (ch >> 3) * 16384, r, ch & 7),
            qsrc + (size_t)(m0 + r) * DK + ch * 4);
        CPA(swc(smb + 32768 + (ch >> 3) * 16384, r, ch & 7),
            ksrc + (size_t)(n0 + r) * DK + ch * 4);
    }
    CPC(); CPW0();
    __syncthreads();

    auto fq = [&](int r, int k) { return (k >> 5) * 4096 + swi(r, k & 31); };
    auto fk = [&](int r, int k) { return 8192 + (k >> 5) * 4096 + swi(r, k & 31); };

    // hoist A (Q) fragments for this warp's 16 rows
    uint32_t a[8][4];
#pragma unroll
    for (int kc = 0; kc < 8; kc++) {
        int k0 = kc * 8 + tg;
        a[kc][0] = __float_as_uint(sm[fq(w * 16 + g,     k0)]);
        a[kc][1] = __float_as_uint(sm[fq(w * 16 + g + 8, k0)]);
        a[kc][2] = __float_as_uint(sm[fq(w * 16 + g,     k0 + 4)]);
        a[kc][3] = __float_as_uint(sm[fq(w * 16 + g + 8, k0 + 4)]);
    }

    float rs0 = 0.f, rs1 = 0.f;
#pragma unroll
    for (int nf = 0; nf < 16; nf++) {
        float acc[4] = {0.f, 0.f, 0.f, 0.f};
#pragma unroll
        for (int kc = 0; kc < 8; kc++) {
            int k0 = kc * 8 + tg;
            uint32_t b[2];
            b[0] = __float_as_uint(sm[fk(nf * 8 + g, k0)]);
            b[1] = __float_as_uint(sm[fk(nf * 8 + g, k0 + 4)]);
            MMA8(acc, a[kc], b);
        }
        rs0 += __expf(acc[0] * 0.125f) + __expf(acc[1] * 0.125f);
        rs1 += __expf(acc[2] * 0.125f) + __expf(acc[3] * 0.125f);
    }
    rs0 += __shfl_xor_sync(0xffffffffu, rs0, 1);
    rs0 += __shfl_xor_sync(0xffffffffu, rs0, 2);
    rs1 += __shfl_xor_sync(0xffffffffu, rs1, 1);
    rs1 += __shfl_xor_sync(0xffffffffu, rs1, 2);
    if (tg == 0) {
        size_t base = (size_t)nt * 65536 + (size_t)bh * SEQ + m0;
        g_psum[base + w * 16 + g]     = rs0;
        g_psum[base + w * 16 + g + 8] = rs1;
    }
}

// ---------------------------------------------------------------------------
// Kernel B: recompute scores, normalize, write weights (coalesced), AV MMA.
// Block = (mtile 128 rows, head); 32 tiles of 64 keys, counted-group pipeline.
// smem floats: Q[0,8192) Kbuf[2][4096]@8192 Vbuf[2][4096]@16384 stage@24576
// total 33280 floats = 133120 B -> 1 CTA/SM.
// ---------------------------------------------------------------------------
__global__ __launch_bounds__(256, 1) void attn_av(float* __restrict__ dout)
{
    extern __shared__ float sm[];
    __shared__ float s_inv[128];
    uint32_t smb = smem_u32(sm);
    const int tid = threadIdx.x;
    const int w = tid >> 5, lane = tid & 31, g = lane >> 2, tg = lane & 3;
    const int mt = blockIdx.x, bh = blockIdx.y;
    const int m0 = mt * 128;
    const int b_ = bh >> 4, h = bh & 15;
    float* wp = head_w_ptr(dout, bh);
    const float* qsrc = g_q  + (size_t)bh * SEQ * DK;
    const float* ksrc = g_k  + (size_t)bh * SEQ * DK;
    const float* vsrc = g_vt + (size_t)bh * DK * SEQ;

    float* stg = sm + 24576 + w * 1088;    // per-warp [16][68]

    // Q load (group 0 includes Q only)
#pragma unroll
    for (int j = 0; j < 8; j++) {
        int idx = tid + 256 * j;
        int r = idx >> 4, ch = idx & 15;
        CPA(swc(smb + (ch >> 3) * 16384, r, ch & 7),
            qsrc + (size_t)(m0 + r) * DK + ch * 4);
    }
    CPC();

    auto loadTile = [&](int t, int buf) {
        uint32_t kb = smb + (8192 + buf * 4096) * 4;
        uint32_t vb = smb + (16384 + buf * 4096) * 4;
#pragma unroll
        for (int i = 0; i < 4; i++) {
            int idx = tid + i * 256;
            int r = idx >> 4, ch = idx & 15;
            CPA(swc(kb + (ch >> 3) * 8192, r, ch & 7),
                ksrc + (size_t)(t * KT + r) * DK + ch * 4);
        }
#pragma unroll
        for (int i = 0; i < 4; i++) {
            int idx = tid + i * 256;
            int d = idx >> 4, ch = idx & 15;
            CPA(swc(vb + (ch >> 3) * 8192, d, ch & 7),
                vsrc + (size_t)d * SEQ + t * KT + ch * 4);
        }
        CPC();
    };

    auto fq  = [&](int r, int k) { return (k >> 5) * 4096 + swi(r, k & 31); };
    auto fkv = [&](int base, int r, int k) { return base + (k >> 5) * 2048 + swi(r, k & 31); };

    // row inverse sums
    if (tid < 128) {
        float s = 0.f;
#pragma unroll
        for (int t = 0; t < 16; t++)
            s += g_psum[(size_t)t * 65536 + (size_t)bh * SEQ + m0 + tid];
        s_inv[tid] = 1.0f / s;
    }

    loadTile(0, 0); loadTile(1, 1);
    __syncthreads();
    const float inv0 = s_inv[w * 16 + g];
    const float inv1 = s_inv[w * 16 + g + 8];

    float oacc[4][2][4];
#pragma unroll
    for (int i = 0; i < 4; i++)
#pragma unroll
        for (int j = 0; j < 2; j++)
#pragma unroll
            for (int e = 0; e < 4; e++) oacc[i][j][e] = 0.f;

    for (int t = 0; t < NT; t++) {
        if (t < NT - 1) { CPW1(); } else { CPW0(); }
        __syncthreads();                       // tile t resident
        const int kbase = 8192 + (t & 1) * 4096;
        const int vbase = 16384 + (t & 1) * 4096;

        // scores for this 64-key tile
        float acc[8][4];
#pragma unroll
        for (int nf = 0; nf < 8; nf++)
#pragma unroll
            for (int e = 0; e < 4; e++) acc[nf][e] = 0.f;
#pragma unroll
        for (int kc = 0; kc < 8; kc++) {
            int k0 = kc * 8 + tg;
            uint32_t a[4];
            a[0] = __float_as_uint(sm[fq(w * 16 + g,     k0)]);
            a[1] = __float_as_uint(sm[fq(w * 16 + g + 8, k0)]);
            a[2] = __float_as_uint(sm[fq(w * 16 + g,     k0 + 4)]);
            a[3] = __float_as_uint(sm[fq(w * 16 + g + 8, k0 + 4)]);
#pragma unroll
            for (int nf = 0; nf < 8; nf++) {
                uint32_t b[2];
                b[0] = __float_as_uint(sm[fkv(kbase, nf * 8 + g, k0)]);
                b[1] = __float_as_uint(sm[fkv(kbase, nf * 8 + g, k0 + 4)]);
                MMA8(acc[nf], a, b);
            }
        }
        // normalized E -> warp-private stage
#pragma unroll
        for (int nf = 0; nf < 8; nf++) {
            float e0 = __expf(acc[nf][0] * 0.125f) * inv0;
            float e1 = __expf(acc[nf][1] * 0.125f) * inv0;
            float e2 = __expf(acc[nf][2] * 0.125f) * inv1;
            float e3 = __expf(acc[nf][3] * 0.125f) * inv1;
            *(float2*)&stg[g * 68 + nf * 8 + 2 * tg]       = make_float2(e0, e1);
            *(float2*)&stg[(g + 8) * 68 + nf * 8 + 2 * tg] = make_float2(e2, e3);
        }
        __syncwarp();
        // coalesced fp32 weight write
#pragma unroll
        for (int i = 0; i < 8; i++) {
            int idx = lane + i * 32;
            int q = idx >> 4, c = (idx & 15) * 4;
            float4 v = *(float4*)&stg[q * 68 + c];
            *(float4*)&wp[(size_t)(m0 + w * 16 + q) * SEQ + t * KT + c] = v;
        }
        // AV: O^T += V^T(tile) @ E^T
#pragma unroll
        for (int kc = 0; kc < 8; kc++) {
            int k0 = kc * 8 + tg;
            uint32_t bf[2][2];
#pragma unroll
            for (int qc = 0; qc < 2; qc++) {
                bf[qc][0] = __float_as_uint(to_tf32(stg[(qc * 8 + g) * 68 + k0]));
                bf[qc][1] = __float_as_uint(to_tf32(stg[(qc * 8 + g) * 68 + k0 + 4]));
            }
#pragma unroll
            for (int mf = 0; mf < 4; mf++) {
                uint32_t a[4];
                a[0] = __float_as_uint(sm[fkv(vbase, mf * 16 + g,     k0)]);
                a[1] = __float_as_uint(sm[fkv(vbase, mf * 16 + g + 8, k0)]);
                a[2] = __float_as_uint(sm[fkv(vbase, mf * 16 + g,     k0 + 4)]);
                a[3] = __float_as_uint(sm[fkv(vbase, mf * 16 + g + 8, k0 + 4)]);
#pragma unroll
                for (int qc = 0; qc < 2; qc++) MMA8(oacc[mf][qc], a, bf[qc]);
            }
        }
        __syncthreads();                       // done with buffers t&1
        if (t + 2 < NT) loadTile(t + 2, t & 1);
    }

    // epilogue: O^T -> stage transpose -> g_attn
    __syncwarp();
#pragma unroll
    for (int mf = 0; mf < 4; mf++)
#pragma unroll
        for (int qc = 0; qc < 2; qc++) {
            stg[(qc * 8 + 2 * tg) * 68     + mf * 16 + g]     = oacc[mf][qc][0];
            stg[(qc * 8 + 2 * tg + 1) * 68 + mf * 16 + g]     = oacc[mf][qc][1];
            stg[(qc * 8 + 2 * tg) * 68     + mf * 16 + g + 8] = oacc[mf][qc][2];
            stg[(qc * 8 + 2 * tg + 1) * 68 + mf * 16 + g + 8] = oacc[mf][qc][3];
        }
    __syncwarp();
#pragma unroll
    for (int i = 0; i < 8; i++) {
        int idx = lane + i * 32;
        int q = idx >> 4, c = (idx & 15) * 4;
        float4 v = *(float4*)&stg[q * 68 + c];
        *(float4*)&g_attn[((size_t)b_ * SEQ + m0 + w * 16 + q) * DM + h * DK + c] = v;
    }
}

// ---------------------------------------------------------------------------
extern "C" void kernel_launch(void* const* d_in, const int* in_sizes, int n_in,
                              void* d_out, int out_size)
{
    const float* x  = (const float*)d_in[0];
    const float* Wq = (const float*)d_in[2];
    const float* bq = (const float*)d_in[3];
    const float* Wk = (const float*)d_in[4];
    const float* bk = (const float*)d_in[5];
    const float* Wv = (const float*)d_in[6];
    const float* bv = (const float*)d_in[7];
    const float* Wo = (const float*)d_in[8];
    const float* bo = (const float*)d_in[9];
    float* out = (float*)d_out;

    cudaFuncSetAttribute(proj_mm,  cudaFuncAttributeMaxDynamicSharedMemorySize, 65536);
    cudaFuncSetAttribute(rowsum_k, cudaFuncAttributeMaxDynamicSharedMemorySize, 65536);
    cudaFuncSetAttribute(attn_av,  cudaFuncAttributeMaxDynamicSharedMemorySize, 133120);

    round_x<<<4096, 256>>>((const float4*)x);
    transpose_w<<<dim3(32, 32, 4), dim3(32, 8)>>>(Wq, Wk, Wv, Wo);

    proj_mm<<<dim3(8, 32, 3), 256, 65536>>>(bq, bk, bv, nullptr, 0);   // QKV fused
    rowsum_k<<<dim3(16, 16, 32), 256, 65536>>>();
    attn_av<<<dim3(16, 32), 256, 133120>>>(out);
    proj_mm<<<dim3(8, 32, 1), 256, 65536>>>(bo, bo, bo, out, 3);       // out-proj
}

// round 8
// speedup vs baseline: 1.3143x; 1.0606x over previous
#include <cuda_runtime.h>
#include <cstdint>
#include <math.h>

#define BATCH 2
#define SEQ   2048
#define NH    16
#define DK    64
#define DM    1024
#define MTOT  4096
#define KT    64
#define NT    32

#define STD_OFF  4194304ull
#define SPEC_OFF 104857600ull

// ------------- scratch (no allocations allowed) -------------
__device__ float g_xr[(size_t)MTOT*DM];             // tf32(x)
__device__ float g_wt[(size_t)4*DM*DM];             // W^T tf32 (q,k,v,o)
__device__ float g_q [(size_t)BATCH*NH*SEQ*DK];     // [B,H,S,Dk] tf32
__device__ float g_k [(size_t)BATCH*NH*SEQ*DK];
__device__ float g_vt[(size_t)BATCH*NH*DK*SEQ];     // [B,H,Dk,S] tf32
__device__ float g_attn[(size_t)MTOT*DM];           // fp32
__device__ float g_psum[(size_t)16*BATCH*NH*SEQ];   // partial row sums per n-tile

// ------------- helpers -------------
__device__ __forceinline__ float to_tf32(float x) {
    float r; asm("cvt.rna.tf32.f32 %0, %1;" : "=f"(r) : "f"(x)); return r;
}
__device__ __forceinline__ uint32_t smem_u32(const void* p) {
    uint32_t a;
    asm("{ .reg .u64 t; cvta.to.shared.u64 t, %1; cvt.u32.u64 %0, t; }" : "=r"(a) : "l"(p));
    return a;
}
#define CPA(d, s) asm volatile("cp.async.cg.shared.global [%0], [%1], 16;" :: "r"(d), "l"(s))
#define CPC()  asm volatile("cp.async.commit_group;")
#define CPW0() asm volatile("cp.async.wait_group 0;" ::: "memory")
#define CPW1() asm volatile("cp.async.wait_group 1;" ::: "memory")

#define MMA8(d, a, b) \
    asm volatile("mma.sync.aligned.m16n8k8.row.col.f32.tf32.tf32.f32 " \
        "{%0,%1,%2,%3}, {%4,%5,%6,%7}, {%8,%9}, {%0,%1,%2,%3};" \
        : "+f"((d)[0]), "+f"((d)[1]), "+f"((d)[2]), "+f"((d)[3]) \
        : "r"((a)[0]), "r"((a)[1]), "r"((a)[2]), "r"((a)[3]), "r"((b)[0]), "r"((b)[1]))

__device__ __forceinline__ int swi(int row, int kk) {
    return row * 32 + (((kk >> 2) ^ (row & 7)) << 2) + (kk & 3);
}
__device__ __forceinline__ uint32_t swc(uint32_t base, int row, int c) {
    return base + row * 128 + ((c ^ (row & 7)) << 4);
}

__device__ __forceinline__ float* head_w_ptr(float* dout, int bh) {
    int b = bh >> 4, h = bh & 15;
    size_t off;
    if (h < 12) off = STD_OFF  + ((size_t)(b * 12 + h)) * SEQ * SEQ;
    else        off = SPEC_OFF + ((size_t)(b * 4 + (h - 12))) * SEQ * SEQ;
    return dout + off;
}

// ---------------------------------------------------------------------------
__global__ __launch_bounds__(256) void round_x(const float4* __restrict__ x)
{
    int i = blockIdx.x * 256 + threadIdx.x;
    float4 v = x[i];
    v.x = to_tf32(v.x); v.y = to_tf32(v.y); v.z = to_tf32(v.z); v.w = to_tf32(v.w);
    ((float4*)g_xr)[i] = v;
}

__global__ __launch_bounds__(256) void transpose_w(
    const float* __restrict__ w0, const float* __restrict__ w1,
    const float* __restrict__ w2, const float* __restrict__ w3)
{
    __shared__ float t[32][33];
    int z = blockIdx.z;
    const float* src = (z == 0) ? w0 : (z == 1) ? w1 : (z == 2) ? w2 : w3;
    float* dst = g_wt + (size_t)z * DM * DM;
    int x = blockIdx.x * 32 + threadIdx.x;
    int y0 = blockIdx.y * 32;
    for (int i = threadIdx.y; i < 32; i += 8)
        t[i][threadIdx.x] = src[(size_t)(y0 + i) * DM + x];
    __syncthreads();
    int kx = y0 + threadIdx.x;
    int n0 = blockIdx.x * 32;
    for (int i = threadIdx.y; i < 32; i += 8)
        dst[(size_t)(n0 + i) * DM + kx] = to_tf32(t[threadIdx.x][i]);
}

// ---------------------------------------------------------------------------
// Projection GEMM: C[4096,1024] = A @ W^T + bias. Block 128x128, K=1024.
// mode 0: QKV fused (which = blockIdx.z); mode 3: out-proj.
// ---------------------------------------------------------------------------
__global__ __launch_bounds__(256, 2) void proj_mm(
    const float* __restrict__ b0, const float* __restrict__ b1,
    const float* __restrict__ b2, float* __restrict__ Cout, int mode)
{
    extern __shared__ float sm[];
    uint32_t smb = smem_u32(sm);
    const int tid = threadIdx.x;
    const int w = tid >> 5, lane = tid & 31, g = lane >> 2, tg = lane & 3;
    const int wm = w >> 2, wn = w & 3;
    const int bn = blockIdx.x * 128, bm = blockIdx.y * 128;
    const int which = (mode == 3) ? 3 : (int)blockIdx.z;
    const float* bias = (which == 0) ? b0 : (which == 1) ? b1 : (which == 2) ? b2 : b0;
    const float* Ap = (which == 3) ? (const float*)g_attn : (const float*)g_xr;
    const float* Wt = g_wt + (size_t)which * DM * DM;

    float acc[4][4][4];
#pragma unroll
    for (int i = 0; i < 4; i++)
#pragma unroll
        for (int j = 0; j < 4; j++)
#pragma unroll
            for (int e = 0; e < 4; e++) acc[i][j][e] = 0.f;

    const int r8 = tid >> 3, c8 = tid & 7;
    auto load = [&](int c, int buf) {
        const float* as = Ap + (size_t)bm * DM + c * 32;
        const float* bs = Wt + (size_t)bn * DM + c * 32;
        uint32_t ab = smb + buf * 16384, bb = smb + 32768 + buf * 16384;
#pragma unroll
        for (int j = 0; j < 4; j++) {
            int r = r8 + 32 * j;
            CPA(swc(ab, r, c8), as + (size_t)r * DM + c8 * 4);
            CPA(swc(bb, r, c8), bs + (size_t)r * DM + c8 * 4);
        }
        CPC();
    };
    auto compute = [&](int buf) {
        const float* A = sm + buf * 4096;
        const float* B = sm + 8192 + buf * 4096;
#pragma unroll
        for (int ks = 0; ks < 4; ks++) {
            int k0 = ks * 8;
            uint32_t a[4][4], b[4][2];
#pragma unroll
            for (int mf = 0; mf < 4; mf++) {
                int row = wm * 64 + mf * 16 + g;
                a[mf][0] = __float_as_uint(A[swi(row,     k0 + tg)]);
                a[mf][1] = __float_as_uint(A[swi(row + 8, k0 + tg)]);
                a[mf][2] = __float_as_uint(A[swi(row,     k0 + 4 + tg)]);
                a[mf][3] = __float_as_uint(A[swi(row + 8, k0 + 4 + tg)]);
            }
#pragma unroll
            for (int nf = 0; nf < 4; nf++) {
                int rn = wn * 32 + nf * 8 + g;
                b[nf][0] = __float_as_uint(B[swi(rn, k0 + tg)]);
                b[nf][1] = __float_as_uint(B[swi(rn, k0 + 4 + tg)]);
            }
#pragma unroll
            for (int mf = 0; mf < 4; mf++)
#pragma unroll
                for (int nf = 0; nf < 4; nf++)
                    MMA8(acc[mf][nf], a[mf], b[nf]);
        }
    };

    load(0, 0); load(1, 1);
    const int NC = DM / 32;
    for (int c = 0; c < NC; c++) {
        if (c < NC - 1) { CPW1(); } else { CPW0(); }
        __syncthreads();
        compute(c & 1);
        __syncthreads();
        if (c + 2 < NC) load(c + 2, c & 1);
    }

#pragma unroll
    for (int mf = 0; mf < 4; mf++)
#pragma unroll
    for (int half = 0; half < 2; half++) {
        int m = bm + wm * 64 + mf * 16 + g + half * 8;
#pragma unroll
        for (int nf = 0; nf < 4; nf++) {
            int n = bn + wn * 32 + nf * 8 + 2 * tg;
            float v0 = acc[mf][nf][2 * half]     + bias[n];
            float v1 = acc[mf][nf][2 * half + 1] + bias[n + 1];
            if (which == 3) {
                *(float2*)(Cout + (size_t)m * DM + n) = make_float2(v0, v1);
            } else {
                int b_ = m >> 11, s = m & 2047, h = n >> 6, d = n & 63;
                if (which == 2) {
                    g_vt[(((size_t)(b_ * NH + h)) * DK + d)     * SEQ + s] = to_tf32(v0);
                    g_vt[(((size_t)(b_ * NH + h)) * DK + d + 1) * SEQ + s] = to_tf32(v1);
                } else {
                    float* qk = which ? g_k : g_q;
                    *(float2*)(qk + (((size_t)(b_ * NH + h)) * SEQ + s) * DK + d) =
                        make_float2(to_tf32(v0), to_tf32(v1));
                }
            }
        }
    }
}

// ---------------------------------------------------------------------------
// Kernel A: rowsum. Block = (ntile 128 keys, mtile 128 rows, head).
// ---------------------------------------------------------------------------
__global__ __launch_bounds__(256, 2) void rowsum_k()
{
    extern __shared__ float sm[];
    uint32_t smb = smem_u32(sm);
    const int tid = threadIdx.x;
    const int w = tid >> 5, lane = tid & 31, g = lane >> 2, tg = lane & 3;
    const int nt = blockIdx.x, mt = blockIdx.y, bh = blockIdx.z;
    const int n0 = nt * 128, m0 = mt * 128;
    const float* qsrc = g_q + (size_t)bh * SEQ * DK;
    const float* ksrc = g_k + (size_t)bh * SEQ * DK;

#pragma unroll
    for (int j = 0; j < 8; j++) {
        int idx = tid + 256 * j;
        int r = idx >> 4, ch = idx & 15;
        CPA(swc(smb + (ch >> 3) * 16384, r, ch & 7),
            qsrc + (size_t)(m0 + r) * DK + ch * 4);
        CPA(swc(smb + 32768 + (ch >> 3) * 16384, r, ch & 7),
            ksrc + (size_t)(n0 + r) * DK + ch * 4);
    }
    CPC(); CPW0();
    __syncthreads();

    auto fq = [&](int r, int k) { return (k >> 5) * 4096 + swi(r, k & 31); };
    auto fk = [&](int r, int k) { return 8192 + (k >> 5) * 4096 + swi(r, k & 31); };

    uint32_t a[8][4];
#pragma unroll
    for (int kc = 0; kc < 8; kc++) {
        int k0 = kc * 8 + tg;
        a[kc][0] = __float_as_uint(sm[fq(w * 16 + g,     k0)]);
        a[kc][1] = __float_as_uint(sm[fq(w * 16 + g + 8, k0)]);
        a[kc][2] = __float_as_uint(sm[fq(w * 16 + g,     k0 + 4)]);
        a[kc][3] = __float_as_uint(sm[fq(w * 16 + g + 8, k0 + 4)]);
    }

    float rs0 = 0.f, rs1 = 0.f;
#pragma unroll
    for (int nf = 0; nf < 16; nf++) {
        float acc[4] = {0.f, 0.f, 0.f, 0.f};
#pragma unroll
        for (int kc = 0; kc < 8; kc++) {
            int k0 = kc * 8 + tg;
            uint32_t b[2];
            b[0] = __float_as_uint(sm[fk(nf * 8 + g, k0)]);
            b[1] = __float_as_uint(sm[fk(nf * 8 + g, k0 + 4)]);
            MMA8(acc, a[kc], b);
        }
        rs0 += __expf(acc[0] * 0.125f) + __expf(acc[1] * 0.125f);
        rs1 += __expf(acc[2] * 0.125f) + __expf(acc[3] * 0.125f);
    }
    rs0 += __shfl_xor_sync(0xffffffffu, rs0, 1);
    rs0 += __shfl_xor_sync(0xffffffffu, rs0, 2);
    rs1 += __shfl_xor_sync(0xffffffffu, rs1, 1);
    rs1 += __shfl_xor_sync(0xffffffffu, rs1, 2);
    if (tg == 0) {
        size_t base = (size_t)nt * 65536 + (size_t)bh * SEQ + m0;
        g_psum[base + w * 16 + g]     = rs0;
        g_psum[base + w * 16 + g + 8] = rs1;
    }
}

// ---------------------------------------------------------------------------
// Kernel B: recompute scores, normalize, write weights, AV MMA.
// Q fragments hoisted to registers; Q smem region reused as stage -> 100352 B
// dyn smem -> 2 CTAs/SM.
// floats: K[2][4096]@0  V[2][4096]@8192  Q/stage@16384 (8704)
// ---------------------------------------------------------------------------
__global__ __launch_bounds__(256, 2) void attn_av(float* __restrict__ dout)
{
    extern __shared__ float sm[];
    __shared__ float s_inv[128];
    uint32_t smb = smem_u32(sm);
    const int tid = threadIdx.x;
    const int w = tid >> 5, lane = tid & 31, g = lane >> 2, tg = lane & 3;
    const int mt = blockIdx.x, bh = blockIdx.y;
    const int m0 = mt * 128;
    const int b_ = bh >> 4, h = bh & 15;
    float* wp = head_w_ptr(dout, bh);
    const float* qsrc = g_q  + (size_t)bh * SEQ * DK;
    const float* ksrc = g_k  + (size_t)bh * SEQ * DK;
    const float* vsrc = g_vt + (size_t)bh * DK * SEQ;

    const int SQ = 16384;                 // Q panels, later stage
    float* stg = sm + SQ + w * 1088;      // per-warp [16][68]

    auto loadTile = [&](int t, int buf) {
        uint32_t kb = smb + buf * 16384;
        uint32_t vb = smb + 32768 + buf * 16384;
#pragma unroll
        for (int i = 0; i < 4; i++) {
            int idx = tid + i * 256;
            int r = idx >> 4, ch = idx & 15;
            CPA(swc(kb + (ch >> 3) * 8192, r, ch & 7),
                ksrc + (size_t)(t * KT + r) * DK + ch * 4);
        }
#pragma unroll
        for (int i = 0; i < 4; i++) {
            int idx = tid + i * 256;
            int d = idx >> 4, ch = idx & 15;
            CPA(swc(vb + (ch >> 3) * 8192, d, ch & 7),
                vsrc + (size_t)d * SEQ + t * KT + ch * 4);
        }
        CPC();
    };
    auto fq  = [&](int r, int k) { return SQ + (k >> 5) * 4096 + swi(r, k & 31); };
    auto fkv = [&](int base, int r, int k) { return base + (k >> 5) * 2048 + swi(r, k & 31); };

    // Q load (own group), then tile 0
#pragma unroll
    for (int j = 0; j < 8; j++) {
        int idx = tid + 256 * j;
        int r = idx >> 4, ch = idx & 15;
        CPA(swc(smb + SQ * 4 + (ch >> 3) * 16384, r, ch & 7),
            qsrc + (size_t)(m0 + r) * DK + ch * 4);
    }
    CPC();
    loadTile(0, 0);

    // rowsum reduction while loads are in flight
    if (tid < 128) {
        float s = 0.f;
#pragma unroll
        for (int t = 0; t < 16; t++)
            s += g_psum[(size_t)t * 65536 + (size_t)bh * SEQ + m0 + tid];
        s_inv[tid] = 1.0f / s;
    }

    CPW1();            // Q group done (tile0 may be in flight)
    __syncthreads();

    // hoist Q fragments (invariant across all 32 key tiles)
    uint32_t qf[8][4];
#pragma unroll
    for (int kc = 0; kc < 8; kc++) {
        int k0 = kc * 8 + tg;
        qf[kc][0] = __float_as_uint(sm[fq(w * 16 + g,     k0)]);
        qf[kc][1] = __float_as_uint(sm[fq(w * 16 + g + 8, k0)]);
        qf[kc][2] = __float_as_uint(sm[fq(w * 16 + g,     k0 + 4)]);
        qf[kc][3] = __float_as_uint(sm[fq(w * 16 + g + 8, k0 + 4)]);
    }
    const float inv0 = s_inv[w * 16 + g];
    const float inv1 = s_inv[w * 16 + g + 8];
    loadTile(1, 1);

    float oacc[4][2][4];
#pragma unroll
    for (int i = 0; i < 4; i++)
#pragma unroll
        for (int j = 0; j < 2; j++)
#pragma unroll
            for (int e = 0; e < 4; e++) oacc[i][j][e] = 0.f;

    for (int t = 0; t < NT; t++) {
        if (t < NT - 1) { CPW1(); } else { CPW0(); }
        __syncthreads();               // tile t resident; stage safe to write
        const int kbase = (t & 1) * 4096;
        const int vbase = 8192 + (t & 1) * 4096;

        // scores per 8-key fragment: MMA -> exp*inv -> stage
#pragma unroll
        for (int nf = 0; nf < 8; nf++) {
            float acc[4] = {0.f, 0.f, 0.f, 0.f};
#pragma unroll
            for (int kc = 0; kc < 8; kc++) {
                int k0 = kc * 8 + tg;
                uint32_t b[2];
                b[0] = __float_as_uint(sm[fkv(kbase, nf * 8 + g, k0)]);
                b[1] = __float_as_uint(sm[fkv(kbase, nf * 8 + g, k0 + 4)]);
                MMA8(acc, qf[kc], b);
            }
            float e0 = __expf(acc[0] * 0.125f) * inv0;
            float e1 = __expf(acc[1] * 0.125f) * inv0;
            float e2 = __expf(acc[2] * 0.125f) * inv1;
            float e3 = __expf(acc[3] * 0.125f) * inv1;
            *(float2*)&stg[g * 68 + nf * 8 + 2 * tg]       = make_float2(e0, e1);
            *(float2*)&stg[(g + 8) * 68 + nf * 8 + 2 * tg] = make_float2(e2, e3);
        }
        __syncwarp();
        // coalesced fp32 weight write
#pragma unroll
        for (int i = 0; i < 8; i++) {
            int idx = lane + i * 32;
            int q = idx >> 4, c = (idx & 15) * 4;
            float4 v = *(float4*)&stg[q * 68 + c];
            *(float4*)&wp[(size_t)(m0 + w * 16 + q) * SEQ + t * KT + c] = v;
        }
        // AV: O^T += V^T(tile) @ E^T
#pragma unroll
        for (int kc = 0; kc < 8; kc++) {
            int k0 = kc * 8 + tg;
            uint32_t bf[2][2];
#pragma unroll
            for (int qc = 0; qc < 2; qc++) {
                bf[qc][0] = __float_as_uint(to_tf32(stg[(qc * 8 + g) * 68 + k0]));
                bf[qc][1] = __float_as_uint(to_tf32(stg[(qc * 8 + g) * 68 + k0 + 4]));
            }
#pragma unroll
            for (int mf = 0; mf < 4; mf++) {
                uint32_t a[4];
                a[0] = __float_as_uint(sm[fkv(vbase, mf * 16 + g,     k0)]);
                a[1] = __float_as_uint(sm[fkv(vbase, mf * 16 + g + 8, k0)]);
                a[2] = __float_as_uint(sm[fkv(vbase, mf * 16 + g,     k0 + 4)]);
                a[3] = __float_as_uint(sm[fkv(vbase, mf * 16 + g + 8, k0 + 4)]);
#pragma unroll
                for (int qc = 0; qc < 2; qc++) MMA8(oacc[mf][qc], a, bf[qc]);
            }
        }
        __syncthreads();               // buffers t&1 free
        if (t + 2 < NT) loadTile(t + 2, t & 1);
    }

    // epilogue: O^T -> stage transpose -> g_attn (rna-rounded for out-proj MMA)
    __syncwarp();
#pragma unroll
    for (int mf = 0; mf < 4; mf++)
#pragma unroll
        for (int qc = 0; qc < 2; qc++) {
            stg[(qc * 8 + 2 * tg) * 68     + mf * 16 + g]     = to_tf32(oacc[mf][qc][0]);
            stg[(qc * 8 + 2 * tg + 1) * 68 + mf * 16 + g]     = to_tf32(oacc[mf][qc][1]);
            stg[(qc * 8 + 2 * tg) * 68     + mf * 16 + g + 8] = to_tf32(oacc[mf][qc][2]);
            stg[(qc * 8 + 2 * tg + 1) * 68 + mf * 16 + g + 8] = to_tf32(oacc[mf][qc][3]);
        }
    __syncwarp();
#pragma unroll
    for (int i = 0; i < 8; i++) {
        int idx = lane + i * 32;
        int q = idx >> 4, c = (idx & 15) * 4;
        float4 v = *(float4*)&stg[q * 68 + c];
        *(float4*)&g_attn[((size_t)b_ * SEQ + m0 + w * 16 + q) * DM + h * DK + c] = v;
    }
}

// ---------------------------------------------------------------------------
extern "C" void kernel_launch(void* const* d_in, const int* in_sizes, int n_in,
                              void* d_out, int out_size)
{
    const float* x  = (const float*)d_in[0];
    const float* Wq = (const float*)d_in[2];
    const float* bq = (const float*)d_in[3];
    const float* Wk = (const float*)d_in[4];
    const float* bk = (const float*)d_in[5];
    const float* Wv = (const float*)d_in[6];
    const float* bv = (const float*)d_in[7];
    const float* Wo = (const float*)d_in[8];
    const float* bo = (const float*)d_in[9];
    float* out = (float*)d_out;

    cudaFuncSetAttribute(proj_mm,  cudaFuncAttributeMaxDynamicSharedMemorySize, 65536);
    cudaFuncSetAttribute(rowsum_k, cudaFuncAttributeMaxDynamicSharedMemorySize, 65536);
    cudaFuncSetAttribute(attn_av,  cudaFuncAttributeMaxDynamicSharedMemorySize, 100352);

    round_x<<<4096, 256>>>((const float4*)x);
    transpose_w<<<dim3(32, 32, 4), dim3(32, 8)>>>(Wq, Wk, Wv, Wo);

    proj_mm<<<dim3(8, 32, 3), 256, 65536>>>(bq, bk, bv, nullptr, 0);   // QKV fused
    rowsum_k<<<dim3(16, 16, 32), 256, 65536>>>();
    attn_av<<<dim3(16, 32), 256, 100352>>>(out);
    proj_mm<<<dim3(8, 32, 1), 256, 65536>>>(bo, bo, bo, out, 3);       // out-proj
}

// round 9
// speedup vs baseline: 1.4096x; 1.0726x over previous
#include <cuda_runtime.h>
#include <cstdint>
#include <math.h>

#define BATCH 2
#define SEQ   2048
#define NH    16
#define DK    64
#define DM    1024
#define MTOT  4096
#define KT    64
#define NT    32

#define STD_OFF  4194304ull
#define SPEC_OFF 104857600ull

// ------------- scratch (no allocations allowed) -------------
__device__ float g_xr[(size_t)MTOT*DM];             // tf32(x)
__device__ float g_wt[(size_t)4*DM*DM];             // W^T tf32 (q,k,v,o)
__device__ float g_q [(size_t)BATCH*NH*SEQ*DK];     // [B,H,S,Dk] tf32
__device__ float g_k [(size_t)BATCH*NH*SEQ*DK];
__device__ float g_vt[(size_t)BATCH*NH*DK*SEQ];     // [B,H,Dk,S] tf32
__device__ float g_attn[(size_t)MTOT*DM];           // fp32
__device__ float g_psum[(size_t)16*BATCH*NH*SEQ];   // partial row sums per n-tile

// ------------- helpers -------------
__device__ __forceinline__ float to_tf32(float x) {
    float r; asm("cvt.rna.tf32.f32 %0, %1;" : "=f"(r) : "f"(x)); return r;
}
__device__ __forceinline__ uint32_t smem_u32(const void* p) {
    uint32_t a;
    asm("{ .reg .u64 t; cvta.to.shared.u64 t, %1; cvt.u32.u64 %0, t; }" : "=r"(a) : "l"(p));
    return a;
}
#define CPA(d, s) asm volatile("cp.async.cg.shared.global [%0], [%1], 16;" :: "r"(d), "l"(s))
#define CPC()  asm volatile("cp.async.commit_group;")
#define CPW0() asm volatile("cp.async.wait_group 0;" ::: "memory")
#define CPW1() asm volatile("cp.async.wait_group 1;" ::: "memory")

#define MMA8(d, a, b) \
    asm volatile("mma.sync.aligned.m16n8k8.row.col.f32.tf32.tf32.f32 " \
        "{%0,%1,%2,%3}, {%4,%5,%6,%7}, {%8,%9}, {%0,%1,%2,%3};" \
        : "+f"((d)[0]), "+f"((d)[1]), "+f"((d)[2]), "+f"((d)[3]) \
        : "r"((a)[0]), "r"((a)[1]), "r"((a)[2]), "r"((a)[3]), "r"((b)[0]), "r"((b)[1]))

__device__ __forceinline__ int swi(int row, int kk) {
    return row * 32 + (((kk >> 2) ^ (row & 7)) << 2) + (kk & 3);
}
// swizzled intra-row offset for rows with (row & 7) == g
__device__ __forceinline__ int offk(int kk, int g) {
    return (((kk >> 2) ^ g) << 2) + (kk & 3);
}
__device__ __forceinline__ uint32_t swc(uint32_t base, int row, int c) {
    return base + row * 128 + ((c ^ (row & 7)) << 4);
}

__device__ __forceinline__ float* head_w_ptr(float* dout, int bh) {
    int b = bh >> 4, h = bh & 15;
    size_t off;
    if (h < 12) off = STD_OFF  + ((size_t)(b * 12 + h)) * SEQ * SEQ;
    else        off = SPEC_OFF + ((size_t)(b * 4 + (h - 12))) * SEQ * SEQ;
    return dout + off;
}

// ---------------------------------------------------------------------------
__global__ __launch_bounds__(256) void round_x(const float4* __restrict__ x)
{
    int i = blockIdx.x * 256 + threadIdx.x;
    float4 v = x[i];
    v.x = to_tf32(v.x); v.y = to_tf32(v.y); v.z = to_tf32(v.z); v.w = to_tf32(v.w);
    ((float4*)g_xr)[i] = v;
}

__global__ __launch_bounds__(256) void transpose_w(
    const float* __restrict__ w0, const float* __restrict__ w1,
    const float* __restrict__ w2, const float* __restrict__ w3)
{
    __shared__ float t[32][33];
    int z = blockIdx.z;
    const float* src = (z == 0) ? w0 : (z == 1) ? w1 : (z == 2) ? w2 : w3;
    float* dst = g_wt + (size_t)z * DM * DM;
    int x = blockIdx.x * 32 + threadIdx.x;
    int y0 = blockIdx.y * 32;
    for (int i = threadIdx.y; i < 32; i += 8)
        t[i][threadIdx.x] = src[(size_t)(y0 + i) * DM + x];
    __syncthreads();
    int kx = y0 + threadIdx.x;
    int n0 = blockIdx.x * 32;
    for (int i = threadIdx.y; i < 32; i += 8)
        dst[(size_t)(n0 + i) * DM + kx] = to_tf32(t[threadIdx.x][i]);
}

// ---------------------------------------------------------------------------
// Projection GEMM: C[4096,1024] = A @ W^T + bias. Block 128x128, K=1024.
// Warp tile 32x64: wm = w>>1 (4 strips of 32 rows), wn = w&1 (2 of 64 cols).
// 1.5 LDS per MMA.  mode 0: QKV fused (which=blockIdx.z); mode 3: out-proj.
// ---------------------------------------------------------------------------
__global__ __launch_bounds__(256, 2) void proj_mm(
    const float* __restrict__ b0, const float* __restrict__ b1,
    const float* __restrict__ b2, float* __restrict__ Cout, int mode)
{
    extern __shared__ float sm[];
    uint32_t smb = smem_u32(sm);
    const int tid = threadIdx.x;
    const int w = tid >> 5, lane = tid & 31, g = lane >> 2, tg = lane & 3;
    const int wm = w >> 1, wn = w & 1;
    const int bn = blockIdx.x * 128, bm = blockIdx.y * 128;
    const int which = (mode == 3) ? 3 : (int)blockIdx.z;
    const float* bias = (which == 0) ? b0 : (which == 1) ? b1 : (which == 2) ? b2 : b0;
    const float* Ap = (which == 3) ? (const float*)g_attn : (const float*)g_xr;
    const float* Wt = g_wt + (size_t)which * DM * DM;

    float acc[2][8][4];
#pragma unroll
    for (int i = 0; i < 2; i++)
#pragma unroll
        for (int j = 0; j < 8; j++)
#pragma unroll
            for (int e = 0; e < 4; e++) acc[i][j][e] = 0.f;

    const int r8 = tid >> 3, c8 = tid & 7;
    auto load = [&](int c, int buf) {
        const float* as = Ap + (size_t)bm * DM + c * 32;
        const float* bs = Wt + (size_t)bn * DM + c * 32;
        uint32_t ab = smb + buf * 16384, bb = smb + 32768 + buf * 16384;
#pragma unroll
        for (int j = 0; j < 4; j++) {
            int r = r8 + 32 * j;
            CPA(swc(ab, r, c8), as + (size_t)r * DM + c8 * 4);
            CPA(swc(bb, r, c8), bs + (size_t)r * DM + c8 * 4);
        }
        CPC();
    };
    auto compute = [&](int buf) {
        const float* A = sm + buf * 4096;
        const float* B = sm + 8192 + buf * 4096;
#pragma unroll
        for (int ks = 0; ks < 4; ks++) {
            int k0 = ks * 8 + tg;
            int o0 = offk(k0, g), o1 = offk(k0 + 4, g);
            uint32_t a[2][4], b[8][2];
#pragma unroll
            for (int mf = 0; mf < 2; mf++) {
                int r = wm * 32 + mf * 16 + g;
                a[mf][0] = __float_as_uint(A[r * 32 + o0]);
                a[mf][1] = __float_as_uint(A[(r + 8) * 32 + o0]);
                a[mf][2] = __float_as_uint(A[r * 32 + o1]);
                a[mf][3] = __float_as_uint(A[(r + 8) * 32 + o1]);
            }
#pragma unroll
            for (int nf = 0; nf < 8; nf++) {
                int rn = wn * 64 + nf * 8 + g;
                b[nf][0] = __float_as_uint(B[rn * 32 + o0]);
                b[nf][1] = __float_as_uint(B[rn * 32 + o1]);
            }
#pragma unroll
            for (int mf = 0; mf < 2; mf++)
#pragma unroll
                for (int nf = 0; nf < 8; nf++)
                    MMA8(acc[mf][nf], a[mf], b[nf]);
        }
    };

    load(0, 0); load(1, 1);
    const int NC = DM / 32;
    for (int c = 0; c < NC; c++) {
        if (c < NC - 1) { CPW1(); } else { CPW0(); }
        __syncthreads();
        compute(c & 1);
        __syncthreads();
        if (c + 2 < NC) load(c + 2, c & 1);
    }

    // epilogue: per warp the 64-col half is one head (which<3 path)
#pragma unroll
    for (int mf = 0; mf < 2; mf++)
#pragma unroll
    for (int half = 0; half < 2; half++) {
        int m = bm + wm * 32 + mf * 16 + g + half * 8;
#pragma unroll
        for (int nf = 0; nf < 8; nf++) {
            int n = bn + wn * 64 + nf * 8 + 2 * tg;
            float v0 = acc[mf][nf][2 * half]     + bias[n];
            float v1 = acc[mf][nf][2 * half + 1] + bias[n + 1];
            if (which == 3) {
                *(float2*)(Cout + (size_t)m * DM + n) = make_float2(v0, v1);
            } else {
                int b_ = m >> 11, s = m & 2047, h = n >> 6, d = n & 63;
                if (which == 2) {
                    g_vt[(((size_t)(b_ * NH + h)) * DK + d)     * SEQ + s] = to_tf32(v0);
                    g_vt[(((size_t)(b_ * NH + h)) * DK + d + 1) * SEQ + s] = to_tf32(v1);
                } else {
                    float* qk = which ? g_k : g_q;
                    *(float2*)(qk + (((size_t)(b_ * NH + h)) * SEQ + s) * DK + d) =
                        make_float2(to_tf32(v0), to_tf32(v1));
                }
            }
        }
    }
}

// ---------------------------------------------------------------------------
// Kernel A: rowsum. Block = (ntile 128 keys, mtile 128 rows, head).
// B-fragment addresses precomputed (base + nf*256 immediate).
// ---------------------------------------------------------------------------
__global__ __launch_bounds__(256, 2) void rowsum_k()
{
    extern __shared__ float sm[];
    uint32_t smb = smem_u32(sm);
    const int tid = threadIdx.x;
    const int w = tid >> 5, lane = tid & 31, g = lane >> 2, tg = lane & 3;
    const int nt = blockIdx.x, mt = blockIdx.y, bh = blockIdx.z;
    const int n0 = nt * 128, m0 = mt * 128;
    const float* qsrc = g_q + (size_t)bh * SEQ * DK;
    const float* ksrc = g_k + (size_t)bh * SEQ * DK;

#pragma unroll
    for (int j = 0; j < 8; j++) {
        int idx = tid + 256 * j;
        int r = idx >> 4, ch = idx & 15;
        CPA(swc(smb + (ch >> 3) * 16384, r, ch & 7),
            qsrc + (size_t)(m0 + r) * DK + ch * 4);
        CPA(swc(smb + 32768 + (ch >> 3) * 16384, r, ch & 7),
            ksrc + (size_t)(n0 + r) * DK + ch * 4);
    }
    CPC(); CPW0();
    __syncthreads();

    // hoist Q fragments + precompute K-fragment base indices
    uint32_t a[8][4];
    int kb[8][2];
#pragma unroll
    for (int kc = 0; kc < 8; kc++) {
        int k0 = kc * 8 + tg;
        int p0 = (k0 >> 5) * 4096,        i0 = offk(k0 & 31, g);
        int p1 = ((k0 + 4) >> 5) * 4096,  i1 = offk((k0 + 4) & 31, g);
        int rq = w * 16 + g;
        a[kc][0] = __float_as_uint(sm[p0 + rq * 32 + i0]);
        a[kc][1] = __float_as_uint(sm[p0 + (rq + 8) * 32 + i0]);
        a[kc][2] = __float_as_uint(sm[p1 + rq * 32 + i1]);
        a[kc][3] = __float_as_uint(sm[p1 + (rq + 8) * 32 + i1]);
        kb[kc][0] = 8192 + p0 + g * 32 + i0;
        kb[kc][1] = 8192 + p1 + g * 32 + i1;
    }

    float rs0 = 0.f, rs1 = 0.f;
#pragma unroll
    for (int nf = 0; nf < 16; nf++) {
        float acc[4] = {0.f, 0.f, 0.f, 0.f};
#pragma unroll
        for (int kc = 0; kc < 8; kc++) {
            uint32_t b[2];
            b[0] = __float_as_uint(sm[kb[kc][0] + nf * 256]);
            b[1] = __float_as_uint(sm[kb[kc][1] + nf * 256]);
            MMA8(acc, a[kc], b);
        }
        rs0 += __expf(acc[0] * 0.125f) + __expf(acc[1] * 0.125f);
        rs1 += __expf(acc[2] * 0.125f) + __expf(acc[3] * 0.125f);
    }
    rs0 += __shfl_xor_sync(0xffffffffu, rs0, 1);
    rs0 += __shfl_xor_sync(0xffffffffu, rs0, 2);
    rs1 += __shfl_xor_sync(0xffffffffu, rs1, 1);
    rs1 += __shfl_xor_sync(0xffffffffu, rs1, 2);
    if (tg == 0) {
        size_t base = (size_t)nt * 65536 + (size_t)bh * SEQ + m0;
        g_psum[base + w * 16 + g]     = rs0;
        g_psum[base + w * 16 + g + 8] = rs1;
    }
}

// ---------------------------------------------------------------------------
// Kernel B: recompute scores, normalize, write weights, AV MMA.
// Precomputed k-chunk offsets shared by scores (K) and AV (V) loops.
// floats: K[2][4096]@0  V[2][4096]@8192  Q/stage@16384 (8704)  -> 2 CTAs/SM
// ---------------------------------------------------------------------------
__global__ __launch_bounds__(256, 2) void attn_av(float* __restrict__ dout)
{
    extern __shared__ float sm[];
    __shared__ float s_inv[128];
    uint32_t smb = smem_u32(sm);
    const int tid = threadIdx.x;
    const int w = tid >> 5, lane = tid & 31, g = lane >> 2, tg = lane & 3;
    const int mt = blockIdx.x, bh = blockIdx.y;
    const int m0 = mt * 128;
    const int b_ = bh >> 4, h = bh & 15;
    float* wp = head_w_ptr(dout, bh);
    const float* qsrc = g_q  + (size_t)bh * SEQ * DK;
    const float* ksrc = g_k  + (size_t)bh * SEQ * DK;
    const float* vsrc = g_vt + (size_t)bh * DK * SEQ;

    const int SQ = 16384;
    float* stg = sm + SQ + w * 1088;      // per-warp [16][68]

    auto loadTile = [&](int t, int buf) {
        uint32_t kb_ = smb + buf * 16384;
        uint32_t vb_ = smb + 32768 + buf * 16384;
#pragma unroll
        for (int i = 0; i < 4; i++) {
            int idx = tid + i * 256;
            int r = idx >> 4, ch = idx & 15;
            CPA(swc(kb_ + (ch >> 3) * 8192, r, ch & 7),
                ksrc + (size_t)(t * KT + r) * DK + ch * 4);
        }
#pragma unroll
        for (int i = 0; i < 4; i++) {
            int idx = tid + i * 256;
            int d = idx >> 4, ch = idx & 15;
            CPA(swc(vb_ + (ch >> 3) * 8192, d, ch & 7),
                vsrc + (size_t)d * SEQ + t * KT + ch * 4);
        }
        CPC();
    };

    // Q load, tile 0
#pragma unroll
    for (int j = 0; j < 8; j++) {
        int idx = tid + 256 * j;
        int r = idx >> 4, ch = idx & 15;
        CPA(swc(smb + SQ * 4 + (ch >> 3) * 16384, r, ch & 7),
            qsrc + (size_t)(m0 + r) * DK + ch * 4);
    }
    CPC();
    loadTile(0, 0);

    if (tid < 128) {
        float s = 0.f;
#pragma unroll
        for (int t = 0; t < 16; t++)
            s += g_psum[(size_t)t * 65536 + (size_t)bh * SEQ + m0 + tid];
        s_inv[tid] = 1.0f / s;
    }

    CPW1();
    __syncthreads();

    // hoist Q fragments + shared K/V chunk offsets (rows are 64-float: 2 panels of 2048)
    uint32_t qf[8][4];
    int po[8][2];
#pragma unroll
    for (int kc = 0; kc < 8; kc++) {
        int k0 = kc * 8 + tg;
        int qp0 = (k0 >> 5) * 4096,       qi0 = offk(k0 & 31, g);
        int qp1 = ((k0 + 4) >> 5) * 4096, qi1 = offk((k0 + 4) & 31, g);
        int rq = w * 16 + g;
        qf[kc][0] = __float_as_uint(sm[SQ + qp0 + rq * 32 + qi0]);
        qf[kc][1] = __float_as_uint(sm[SQ + qp0 + (rq + 8) * 32 + qi0]);
        qf[kc][2] = __float_as_uint(sm[SQ + qp1 + rq * 32 + qi1]);
        qf[kc][3] = __float_as_uint(sm[SQ + qp1 + (rq + 8) * 32 + qi1]);
        po[kc][0] = (k0 >> 5) * 2048 + g * 32 + qi0;
        po[kc][1] = ((k0 + 4) >> 5) * 2048 + g * 32 + qi1;
    }
    const float inv0 = s_inv[w * 16 + g];
    const float inv1 = s_inv[w * 16 + g + 8];
    loadTile(1, 1);

    float oacc[4][2][4];
#pragma unroll
    for (int i = 0; i < 4; i++)
#pragma unroll
        for (int j = 0; j < 2; j++)
#pragma unroll
            for (int e = 0; e < 4; e++) oacc[i][j][e] = 0.f;

    for (int t = 0; t < NT; t++) {
        if (t < NT - 1) { CPW1(); } else { CPW0(); }
        __syncthreads();
        const int kbase = (t & 1) * 4096;
        const int vbase = 8192 + (t & 1) * 4096;

        // scores: MMA -> exp*inv -> stage  (b addr = kbase + po + nf*256)
#pragma unroll
        for (int nf = 0; nf < 8; nf++) {
            float acc[4] = {0.f, 0.f, 0.f, 0.f};
#pragma unroll
            for (int kc = 0; kc < 8; kc++) {
                uint32_t b[2];
                b[0] = __float_as_uint(sm[kbase + po[kc][0] + nf * 256]);
                b[1] = __float_as_uint(sm[kbase + po[kc][1] + nf * 256]);
                MMA8(acc, qf[kc], b);
            }
            float e0 = __expf(acc[0] * 0.125f) * inv0;
            float e1 = __expf(acc[1] * 0.125f) * inv0;
            float e2 = __expf(acc[2] * 0.125f) * inv1;
            float e3 = __expf(acc[3] * 0.125f) * inv1;
            *(float2*)&stg[g * 68 + nf * 8 + 2 * tg]       = make_float2(e0, e1);
            *(float2*)&stg[(g + 8) * 68 + nf * 8 + 2 * tg] = make_float2(e2, e3);
        }
        __syncwarp();
        // coalesced fp32 weight write
#pragma unroll
        for (int i = 0; i < 8; i++) {
            int idx = lane + i * 32;
            int q = idx >> 4, c = (idx & 15) * 4;
            float4 v = *(float4*)&stg[q * 68 + c];
            *(float4*)&wp[(size_t)(m0 + w * 16 + q) * SEQ + t * KT + c] = v;
        }
        // AV: O^T += V^T(tile) @ E^T   (a addr = vbase + po + mf*512)
#pragma unroll
        for (int kc = 0; kc < 8; kc++) {
            int k0 = kc * 8 + tg;
            uint32_t bf[2][2];
#pragma unroll
            for (int qc = 0; qc < 2; qc++) {
                bf[qc][0] = __float_as_uint(to_tf32(stg[(qc * 8 + g) * 68 + k0]));
                bf[qc][1] = __float_as_uint(to_tf32(stg[(qc * 8 + g) * 68 + k0 + 4]));
            }
#pragma unroll
            for (int mf = 0; mf < 4; mf++) {
                uint32_t a[4];
                a[0] = __float_as_uint(sm[vbase + po[kc][0] + mf * 512]);
                a[1] = __float_as_uint(sm[vbase + po[kc][0] + mf * 512 + 256]);
                a[2] = __float_as_uint(sm[vbase + po[kc][1] + mf * 512]);
                a[3] = __float_as_uint(sm[vbase + po[kc][1] + mf * 512 + 256]);
#pragma unroll
                for (int qc = 0; qc < 2; qc++) MMA8(oacc[mf][qc], a, bf[qc]);
            }
        }
        __syncthreads();
        if (t + 2 < NT) loadTile(t + 2, t & 1);
    }

    // epilogue: O^T -> stage transpose -> g_attn (rna-rounded for out-proj MMA)
    __syncwarp();
#pragma unroll
    for (int mf = 0; mf < 4; mf++)
#pragma unroll
        for (int qc = 0; qc < 2; qc++) {
            stg[(qc * 8 + 2 * tg) * 68     + mf * 16 + g]     = to_tf32(oacc[mf][qc][0]);
            stg[(qc * 8 + 2 * tg + 1) * 68 + mf * 16 + g]     = to_tf32(oacc[mf][qc][1]);
            stg[(qc * 8 + 2 * tg) * 68     + mf * 16 + g + 8] = to_tf32(oacc[mf][qc][2]);
            stg[(qc * 8 + 2 * tg + 1) * 68 + mf * 16 + g + 8] = to_tf32(oacc[mf][qc][3]);
        }
    __syncwarp();
#pragma unroll
    for (int i = 0; i < 8; i++) {
        int idx = lane + i * 32;
        int q = idx >> 4, c = (idx & 15) * 4;
        float4 v = *(float4*)&stg[q * 68 + c];
        *(float4*)&g_attn[((size_t)b_ * SEQ + m0 + w * 16 + q) * DM + h * DK + c] = v;
    }
}

// ---------------------------------------------------------------------------
extern "C" void kernel_launch(void* const* d_in, const int* in_sizes, int n_in,
                              void* d_out, int out_size)
{
    const float* x  = (const float*)d_in[0];
    const float* Wq = (const float*)d_in[2];
    const float* bq = (const float*)d_in[3];
    const float* Wk = (const float*)d_in[4];
    const float* bk = (const float*)d_in[5];
    const float* Wv = (const float*)d_in[6];
    const float* bv = (const float*)d_in[7];
    const float* Wo = (const float*)d_in[8];
    const float* bo = (const float*)d_in[9];
    float* out = (float*)d_out;

    cudaFuncSetAttribute(proj_mm,  cudaFuncAttributeMaxDynamicSharedMemorySize, 65536);
    cudaFuncSetAttribute(rowsum_k, cudaFuncAttributeMaxDynamicSharedMemorySize, 65536);
    cudaFuncSetAttribute(attn_av,  cudaFuncAttributeMaxDynamicSharedMemorySize, 100352);

    round_x<<<4096, 256>>>((const float4*)x);
    transpose_w<<<dim3(32, 32, 4), dim3(32, 8)>>>(Wq, Wk, Wv, Wo);

    proj_mm<<<dim3(8, 32, 3), 256, 65536>>>(bq, bk, bv, nullptr, 0);   // QKV fused
    rowsum_k<<<dim3(16, 16, 32), 256, 65536>>>();
    attn_av<<<dim3(16, 32), 256, 100352>>>(out);
    proj_mm<<<dim3(8, 32, 1), 256, 65536>>>(bo, bo, bo, out, 3);       // out-proj
}

// round 11
// speedup vs baseline: 1.4522x; 1.0302x over previous
#include <cuda_runtime.h>
#include <cstdint>
#include <math.h>

#define BATCH 2
#define SEQ   2048
#define NH    16
#define DK    64
#define DM    1024
#define MTOT  4096
#define KT    64
#define NT    32

#define STD_OFF  4194304ull
#define SPEC_OFF 104857600ull

// ------------- scratch (no allocations allowed) -------------
__device__ float g_wt[(size_t)4*DM*DM];             // W^T tf32 (q,k,v,o)
__device__ float g_q [(size_t)BATCH*NH*SEQ*DK];     // [B,H,S,Dk] tf32
__device__ float g_k [(size_t)BATCH*NH*SEQ*DK];
__device__ float g_vt[(size_t)BATCH*NH*DK*SEQ];     // [B,H,Dk,S] tf32
__device__ float g_attn[(size_t)MTOT*DM];           // tf32-rounded fp32
__device__ float g_psum[(size_t)16*BATCH*NH*SEQ];   // partial row sums per n-tile

// ------------- helpers -------------
__device__ __forceinline__ float to_tf32(float x) {
    float r; asm("cvt.rna.tf32.f32 %0, %1;" : "=f"(r) : "f"(x)); return r;
}
__device__ __forceinline__ uint32_t smem_u32(const void* p) {
    uint32_t a;
    asm("{ .reg .u64 t; cvta.to.shared.u64 t, %1; cvt.u32.u64 %0, t; }" : "=r"(a) : "l"(p));
    return a;
}
#define CPA(d, s) asm volatile("cp.async.cg.shared.global [%0], [%1], 16;" :: "r"(d), "l"(s))
#define CPC()  asm volatile("cp.async.commit_group;")
#define CPW0() asm volatile("cp.async.wait_group 0;" ::: "memory")
#define CPW1() asm volatile("cp.async.wait_group 1;" ::: "memory")

#define MMA8(d, a, b) \
    asm volatile("mma.sync.aligned.m16n8k8.row.col.f32.tf32.tf32.f32 " \
        "{%0,%1,%2,%3}, {%4,%5,%6,%7}, {%8,%9}, {%0,%1,%2,%3};" \
        : "+f"((d)[0]), "+f"((d)[1]), "+f"((d)[2]), "+f"((d)[3]) \
        : "r"((a)[0]), "r"((a)[1]), "r"((a)[2]), "r"((a)[3]), "r"((b)[0]), "r"((b)[1]))

// swizzled intra-row offset for rows with (row & 7) == g
__device__ __forceinline__ int offk(int kk, int g) {
    return (((kk >> 2) ^ g) << 2) + (kk & 3);
}
__device__ __forceinline__ uint32_t swc(uint32_t base, int row, int c) {
    return base + row * 128 + ((c ^ (row & 7)) << 4);
}

__device__ __forceinline__ float* head_w_ptr(float* dout, int bh) {
    int b = bh >> 4, h = bh & 15;
    size_t off;
    if (h < 12) off = STD_OFF  + ((size_t)(b * 12 + h)) * SEQ * SEQ;
    else        off = SPEC_OFF + ((size_t)(b * 4 + (h - 12))) * SEQ * SEQ;
    return dout + off;
}

// ---------------------------------------------------------------------------
__global__ __launch_bounds__(256) void transpose_w(
    const float* __restrict__ w0, const float* __restrict__ w1,
    const float* __restrict__ w2, const float* __restrict__ w3)
{
    __shared__ float t[32][33];
    int z = blockIdx.z;
    const float* src = (z == 0) ? w0 : (z == 1) ? w1 : (z == 2) ? w2 : w3;
    float* dst = g_wt + (size_t)z * DM * DM;
    int x = blockIdx.x * 32 + threadIdx.x;
    int y0 = blockIdx.y * 32;
    for (int i = threadIdx.y; i < 32; i += 8)
        t[i][threadIdx.x] = src[(size_t)(y0 + i) * DM + x];
    __syncthreads();
    int kx = y0 + threadIdx.x;
    int n0 = blockIdx.x * 32;
    for (int i = threadIdx.y; i < 32; i += 8)
        dst[(size_t)(n0 + i) * DM + kx] = to_tf32(t[threadIdx.x][i]);
}

// ---------------------------------------------------------------------------
// Projection GEMM: C[4096,1024] = A @ W^T + bias. Block 128x128, K=1024.
// Warp tile 32x64.  A-fragments rna-rounded after LDS (x is raw fp32).
// mode 0: QKV fused (which=blockIdx.z); mode 3: out-proj (A = g_attn).
// ---------------------------------------------------------------------------
__global__ __launch_bounds__(256, 2) void proj_mm(
    const float* __restrict__ x,
    const float* __restrict__ b0, const float* __restrict__ b1,
    const float* __restrict__ b2, float* __restrict__ Cout, int mode)
{
    extern __shared__ float sm[];
    uint32_t smb = smem_u32(sm);
    const int tid = threadIdx.x;
    const int w = tid >> 5, lane = tid & 31, g = lane >> 2, tg = lane & 3;
    const int wm = w >> 1, wn = w & 1;
    const int bn = blockIdx.x * 128, bm = blockIdx.y * 128;
    const int which = (mode == 3) ? 3 : (int)blockIdx.z;
    const float* bias = (which == 0) ? b0 : (which == 1) ? b1 : (which == 2) ? b2 : b0;
    const float* Ap = (which == 3) ? (const float*)g_attn : x;
    const float* Wt = g_wt + (size_t)which * DM * DM;

    float acc[2][8][4];
#pragma unroll
    for (int i = 0; i < 2; i++)
#pragma unroll
        for (int j = 0; j < 8; j++)
#pragma unroll
            for (int e = 0; e < 4; e++) acc[i][j][e] = 0.f;

    const int r8 = tid >> 3, c8 = tid & 7;
    auto load = [&](int c, int buf) {
        const float* as = Ap + (size_t)bm * DM + c * 32;
        const float* bs = Wt + (size_t)bn * DM + c * 32;
        uint32_t ab = smb + buf * 16384, bb = smb + 32768 + buf * 16384;
#pragma unroll
        for (int j = 0; j < 4; j++) {
            int r = r8 + 32 * j;
            CPA(swc(ab, r, c8), as + (size_t)r * DM + c8 * 4);
            CPA(swc(bb, r, c8), bs + (size_t)r * DM + c8 * 4);
        }
        CPC();
    };
    auto compute = [&](int buf) {
        const float* A = sm + buf * 4096;
        const float* B = sm + 8192 + buf * 4096;
#pragma unroll
        for (int ks = 0; ks < 4; ks++) {
            int k0 = ks * 8 + tg;
            int o0 = offk(k0, g), o1 = offk(k0 + 4, g);
            uint32_t a[2][4], b[8][2];
#pragma unroll
            for (int mf = 0; mf < 2; mf++) {
                int r = wm * 32 + mf * 16 + g;
                a[mf][0] = __float_as_uint(to_tf32(A[r * 32 + o0]));
                a[mf][1] = __float_as_uint(to_tf32(A[(r + 8) * 32 + o0]));
                a[mf][2] = __float_as_uint(to_tf32(A[r * 32 + o1]));
                a[mf][3] = __float_as_uint(to_tf32(A[(r + 8) * 32 + o1]));
            }
#pragma unroll
            for (int nf = 0; nf < 8; nf++) {
                int rn = wn * 64 + nf * 8 + g;
                b[nf][0] = __float_as_uint(B[rn * 32 + o0]);
                b[nf][1] = __float_as_uint(B[rn * 32 + o1]);
            }
#pragma unroll
            for (int mf = 0; mf < 2; mf++)
#pragma unroll
                for (int nf = 0; nf < 8; nf++)
                    MMA8(acc[mf][nf], a[mf], b[nf]);
        }
    };

    load(0, 0); load(1, 1);
    const int NC = DM / 32;
    for (int c = 0; c < NC; c++) {
        if (c < NC - 1) { CPW1(); } else { CPW0(); }
        __syncthreads();
        compute(c & 1);
        __syncthreads();
        if (c + 2 < NC) load(c + 2, c & 1);
    }

#pragma unroll
    for (int mf = 0; mf < 2; mf++)
#pragma unroll
    for (int half = 0; half < 2; half++) {
        int m = bm + wm * 32 + mf * 16 + g + half * 8;
#pragma unroll
        for (int nf = 0; nf < 8; nf++) {
            int n = bn + wn * 64 + nf * 8 + 2 * tg;
            float v0 = acc[mf][nf][2 * half]     + bias[n];
            float v1 = acc[mf][nf][2 * half + 1] + bias[n + 1];
            if (which == 3) {
                *(float2*)(Cout + (size_t)m * DM + n) = make_float2(v0, v1);
            } else {
                int b_ = m >> 11, s = m & 2047, h = n >> 6, d = n & 63;
                if (which == 2) {
                    g_vt[(((size_t)(b_ * NH + h)) * DK + d)     * SEQ + s] = to_tf32(v0);
                    g_vt[(((size_t)(b_ * NH + h)) * DK + d + 1) * SEQ + s] = to_tf32(v1);
                } else {
                    float* qk = which ? g_k : g_q;
                    *(float2*)(qk + (((size_t)(b_ * NH + h)) * SEQ + s) * DK + d) =
                        make_float2(to_tf32(v0), to_tf32(v1));
                }
            }
        }
    }
}

// ---------------------------------------------------------------------------
// Kernel A: rowsum. Block = (ntile 128 keys, mtile 256 rows, head).
// Warp = 32 rows (2 m-frags share each K fragment -> 1 LDS/MMA).
// smem floats: Q[2][8192] @0 (64KB), K[2][4096] @16384 (32KB)  -> 96KB
// ---------------------------------------------------------------------------
__global__ __launch_bounds__(256, 2) void rowsum_k()
{
    extern __shared__ float sm[];
    uint32_t smb = smem_u32(sm);
    const int tid = threadIdx.x;
    const int w = tid >> 5, lane = tid & 31, g = lane >> 2, tg = lane & 3;
    const int nt = blockIdx.x, mt = blockIdx.y, bh = blockIdx.z;
    const int n0 = nt * 128, m0 = mt * 256;
    const float* qsrc = g_q + (size_t)bh * SEQ * DK;
    const float* ksrc = g_k + (size_t)bh * SEQ * DK;

    // Q: 256 rows x 64 -> 2 panels [256][32] (byte stride 32768)
#pragma unroll
    for (int j = 0; j < 16; j++) {
        int idx = tid + 256 * j;
        int r = idx >> 4, ch = idx & 15;
        CPA(swc(smb + (ch >> 3) * 32768, r, ch & 7),
            qsrc + (size_t)(m0 + r) * DK + ch * 4);
    }
    // K: 128 rows x 64 -> 2 panels [128][32] @ byte 65536
#pragma unroll
    for (int j = 0; j < 8; j++) {
        int idx = tid + 256 * j;
        int r = idx >> 4, ch = idx & 15;
        CPA(swc(smb + 65536 + (ch >> 3) * 16384, r, ch & 7),
            ksrc + (size_t)(n0 + r) * DK + ch * 4);
    }
    CPC(); CPW0();
    __syncthreads();

    // hoist Q fragments for 32 rows (2 m-frags) + K base indices
    uint32_t a[8][8];
    int kb[8][2];
#pragma unroll
    for (int kc = 0; kc < 8; kc++) {
        int k0 = kc * 8 + tg;
        int p0 = (k0 >> 5) * 8192,        i0 = offk(k0 & 31, g);
        int p1 = ((k0 + 4) >> 5) * 8192,  i1 = offk((k0 + 4) & 31, g);
        int rq = w * 32 + g;
        a[kc][0] = __float_as_uint(sm[p0 + rq * 32 + i0]);
        a[kc][1] = __float_as_uint(sm[p0 + (rq + 8) * 32 + i0]);
        a[kc][2] = __float_as_uint(sm[p1 + rq * 32 + i1]);
        a[kc][3] = __float_as_uint(sm[p1 + (rq + 8) * 32 + i1]);
        a[kc][4] = __float_as_uint(sm[p0 + (rq + 16) * 32 + i0]);
        a[kc][5] = __float_as_uint(sm[p0 + (rq + 24) * 32 + i0]);
        a[kc][6] = __float_as_uint(sm[p1 + (rq + 16) * 32 + i1]);
        a[kc][7] = __float_as_uint(sm[p1 + (rq + 24) * 32 + i1]);
        kb[kc][0] = 16384 + (k0 >> 5) * 4096 + g * 32 + i0;
        kb[kc][1] = 16384 + ((k0 + 4) >> 5) * 4096 + g * 32 + i1;
    }

    float rs[4] = {0.f, 0.f, 0.f, 0.f};
#pragma unroll
    for (int nf = 0; nf < 16; nf++) {
        float ac0[4] = {0.f, 0.f, 0.f, 0.f};
        float ac1[4] = {0.f, 0.f, 0.f, 0.f};
#pragma unroll
        for (int kc = 0; kc < 8; kc++) {
            uint32_t b[2];
            b[0] = __float_as_uint(sm[kb[kc][0] + nf * 256]);
            b[1] = __float_as_uint(sm[kb[kc][1] + nf * 256]);
            MMA8(ac0, a[kc], b);
            MMA8(ac1, (a[kc] + 4), b);
        }
        rs[0] += __expf(ac0[0] * 0.125f) + __expf(ac0[1] * 0.125f);
        rs[1] += __expf(ac0[2] * 0.125f) + __expf(ac0[3] * 0.125f);
        rs[2] += __expf(ac1[0] * 0.125f) + __expf(ac1[1] * 0.125f);
        rs[3] += __expf(ac1[2] * 0.125f) + __expf(ac1[3] * 0.125f);
    }
#pragma unroll
    for (int i = 0; i < 4; i++) {
        rs[i] += __shfl_xor_sync(0xffffffffu, rs[i], 1);
        rs[i] += __shfl_xor_sync(0xffffffffu, rs[i], 2);
    }
    if (tg == 0) {
        size_t base = (size_t)nt * 65536 + (size_t)bh * SEQ + m0 + w * 32 + g;
        g_psum[base]      = rs[0];
        g_psum[base + 8]  = rs[1];
        g_psum[base + 16] = rs[2];
        g_psum[base + 24] = rs[3];
    }
}

// ---------------------------------------------------------------------------
// Kernel B: recompute scores, normalize, AV MMA, weight write.
// floats: K[2][4096]@0  V[2][4096]@8192  Q/stage@16384 (8704)  -> 2 CTAs/SM
// ---------------------------------------------------------------------------
__global__ __launch_bounds__(256, 2) void attn_av(float* __restrict__ dout)
{
    extern __shared__ float sm[];
    __shared__ float s_inv[128];
    uint32_t smb = smem_u32(sm);
    const int tid = threadIdx.x;
    const int w = tid >> 5, lane = tid & 31, g = lane >> 2, tg = lane & 3;
    const int mt = blockIdx.x, bh = blockIdx.y;
    const int m0 = mt * 128;
    const int b_ = bh >> 4, h = bh & 15;
    float* wp = head_w_ptr(dout, bh);
    const float* qsrc = g_q  + (size_t)bh * SEQ * DK;
    const float* ksrc = g_k  + (size_t)bh * SEQ * DK;
    const float* vsrc = g_vt + (size_t)bh * DK * SEQ;

    const int SQ = 16384;
    float* stg = sm + SQ + w * 1088;      // per-warp [16][68]

    auto loadTile = [&](int t, int buf) {
        uint32_t kb_ = smb + buf * 16384;
        uint32_t vb_ = smb + 32768 + buf * 16384;
#pragma unroll
        for (int i = 0; i < 4; i++) {
            int idx = tid + i * 256;
            int r = idx >> 4, ch = idx & 15;
            CPA(swc(kb_ + (ch >> 3) * 8192, r, ch & 7),
                ksrc + (size_t)(t * KT + r) * DK + ch * 4);
        }
#pragma unroll
        for (int i = 0; i < 4; i++) {
            int idx = tid + i * 256;
            int d = idx >> 4, ch = idx & 15;
            CPA(swc(vb_ + (ch >> 3) * 8192, d, ch & 7),
                vsrc + (size_t)d * SEQ + t * KT + ch * 4);
        }
        CPC();
    };

    // Q load, tile 0
#pragma unroll
    for (int j = 0; j < 8; j++) {
        int idx = tid + 256 * j;
        int r = idx >> 4, ch = idx & 15;
        CPA(swc(smb + SQ * 4 + (ch >> 3) * 16384, r, ch & 7),
            qsrc + (size_t)(m0 + r) * DK + ch * 4);
    }
    CPC();
    loadTile(0, 0);

    if (tid < 128) {
        float s = 0.f;
#pragma unroll
        for (int t = 0; t < 16; t++)
            s += g_psum[(size_t)t * 65536 + (size_t)bh * SEQ + m0 + tid];
        s_inv[tid] = 1.0f / s;
    }

    CPW1();
    __syncthreads();

    uint32_t qf[8][4];
    int po[8][2];
#pragma unroll
    for (int kc = 0; kc < 8; kc++) {
        int k0 = kc * 8 + tg;
        int qp0 = (k0 >> 5) * 4096,       qi0 = offk(k0 & 31, g);
        int qp1 = ((k0 + 4) >> 5) * 4096, qi1 = offk((k0 + 4) & 31, g);
        int rq = w * 16 + g;
        qf[kc][0] = __float_as_uint(sm[SQ + qp0 + rq * 32 + qi0]);
        qf[kc][1] = __float_as_uint(sm[SQ + qp0 + (rq + 8) * 32 + qi0]);
        qf[kc][2] = __float_as_uint(sm[SQ + qp1 + rq * 32 + qi1]);
        qf[kc][3] = __float_as_uint(sm[SQ + qp1 + (rq + 8) * 32 + qi1]);
        po[kc][0] = (k0 >> 5) * 2048 + g * 32 + qi0;
        po[kc][1] = ((k0 + 4) >> 5) * 2048 + g * 32 + qi1;
    }
    const float inv0 = s_inv[w * 16 + g];
    const float inv1 = s_inv[w * 16 + g + 8];
    loadTile(1, 1);

    float oacc[4][2][4];
#pragma unroll
    for (int i = 0; i < 4; i++)
#pragma unroll
        for (int j = 0; j < 2; j++)
#pragma unroll
            for (int e = 0; e < 4; e++) oacc[i][j][e] = 0.f;

    for (int t = 0; t < NT; t++) {
        if (t < NT - 1) { CPW1(); } else { CPW0(); }
        __syncthreads();
        const int kbase = (t & 1) * 4096;
        const int vbase = 8192 + (t & 1) * 4096;

        // scores: MMA -> exp*inv -> stage
#pragma unroll
        for (int nf = 0; nf < 8; nf++) {
            float acc[4] = {0.f, 0.f, 0.f, 0.f};
#pragma unroll
            for (int kc = 0; kc < 8; kc++) {
                uint32_t b[2];
                b[0] = __float_as_uint(sm[kbase + po[kc][0] + nf * 256]);
                b[1] = __float_as_uint(sm[kbase + po[kc][1] + nf * 256]);
                MMA8(acc, qf[kc], b);
            }
            float e0 = __expf(acc[0] * 0.125f) * inv0;
            float e1 = __expf(acc[1] * 0.125f) * inv0;
            float e2 = __expf(acc[2] * 0.125f) * inv1;
            float e3 = __expf(acc[3] * 0.125f) * inv1;
            *(float2*)&stg[g * 68 + nf * 8 + 2 * tg]       = make_float2(e0, e1);
            *(float2*)&stg[(g + 8) * 68 + nf * 8 + 2 * tg] = make_float2(e2, e3);
        }
        __syncwarp();
        // AV first (feed tensor pipe), then weight STG drains in its shadow
#pragma unroll
        for (int kc = 0; kc < 8; kc++) {
            int k0 = kc * 8 + tg;
            uint32_t bf[2][2];
#pragma unroll
            for (int qc = 0; qc < 2; qc++) {
                bf[qc][0] = __float_as_uint(to_tf32(stg[(qc * 8 + g) * 68 + k0]));
                bf[qc][1] = __float_as_uint(to_tf32(stg[(qc * 8 + g) * 68 + k0 + 4]));
            }
#pragma unroll
            for (int mf = 0; mf < 4; mf++) {
                uint32_t a[4];
                a[0] = __float_as_uint(sm[vbase + po[kc][0] + mf * 512]);
                a[1] = __float_as_uint(sm[vbase + po[kc][0] + mf * 512 + 256]);
                a[2] = __float_as_uint(sm[vbase + po[kc][1] + mf * 512]);
                a[3] = __float_as_uint(sm[vbase + po[kc][1] + mf * 512 + 256]);
#pragma unroll
                for (int qc = 0; qc < 2; qc++) MMA8(oacc[mf][qc], a, bf[qc]);
            }
        }
        // coalesced fp32 weight write
#pragma unroll
        for (int i = 0; i < 8; i++) {
            int idx = lane + i * 32;
            int q = idx >> 4, c = (idx & 15) * 4;
            float4 v = *(float4*)&stg[q * 68 + c];
            *(float4*)&wp[(size_t)(m0 + w * 16 + q) * SEQ + t * KT + c] = v;
        }
        __syncthreads();
        if (t + 2 < NT) loadTile(t + 2, t & 1);
    }

    // epilogue: O^T -> stage transpose -> g_attn (rna-rounded for out-proj)
    __syncwarp();
#pragma unroll
    for (int mf = 0; mf < 4; mf++)
#pragma unroll
        for (int qc = 0; qc < 2; qc++) {
            stg[(qc * 8 + 2 * tg) * 68     + mf * 16 + g]     = to_tf32(oacc[mf][qc][0]);
            stg[(qc * 8 + 2 * tg + 1) * 68 + mf * 16 + g]     = to_tf32(oacc[mf][qc][1]);
            stg[(qc * 8 + 2 * tg) * 68     + mf * 16 + g + 8] = to_tf32(oacc[mf][qc][2]);
            stg[(qc * 8 + 2 * tg + 1) * 68 + mf * 16 + g + 8] = to_tf32(oacc[mf][qc][3]);
        }
    __syncwarp();
#pragma unroll
    for (int i = 0; i < 8; i++) {
        int idx = lane + i * 32;
        int q = idx >> 4, c = (idx & 15) * 4;
        float4 v = *(float4*)&stg[q * 68 + c];
        *(float4*)&g_attn[((size_t)b_ * SEQ + m0 + w * 16 + q) * DM + h * DK + c] = v;
    }
}

// ---------------------------------------------------------------------------
extern "C" void kernel_launch(void* const* d_in, const int* in_sizes, int n_in,
                              void* d_out, int out_size)
{
    const float* x  = (const float*)d_in[0];
    const float* Wq = (const float*)d_in[2];
    const float* bq = (const float*)d_in[3];
    const float* Wk = (const float*)d_in[4];
    const float* bk = (const float*)d_in[5];
    const float* Wv = (const float*)d_in[6];
    const float* bv = (const float*)d_in[7];
    const float* Wo = (const float*)d_in[8];
    const float* bo = (const float*)d_in[9];
    float* out = (float*)d_out;

    cudaFuncSetAttribute(proj_mm,  cudaFuncAttributeMaxDynamicSharedMemorySize, 65536);
    cudaFuncSetAttribute(rowsum_k, cudaFuncAttributeMaxDynamicSharedMemorySize, 98304);
    cudaFuncSetAttribute(attn_av,  cudaFuncAttributeMaxDynamicSharedMemorySize, 100352);

    transpose_w<<<dim3(32, 32, 4), dim3(32, 8)>>>(Wq, Wk, Wv, Wo);

    proj_mm<<<dim3(8, 32, 3), 256, 65536>>>(x, bq, bk, bv, nullptr, 0);   // QKV fused
    rowsum_k<<<dim3(16, 8, 32), 256, 98304>>>();
    attn_av<<<dim3(16, 32), 256, 100352>>>(out);
    proj_mm<<<dim3(8, 32, 1), 256, 65536>>>(x, bo, bo, bo, out, 3);       // out-proj
}